// round 12
// baseline (speedup 1.0000x reference)
#include <cuda_runtime.h>
#include <cuda_bf16.h>
#include <cstdint>

// ---------------------------------------------------------------------------
// MultiHeadAttention: B=16, L=512, D=512, H=8, DK=DV=64, TEMP=8
// out = ( output[16,512], attn[128,512,512] ) concatenated in d_out (fp32)
// R11: fc v4 — 64-o blocks, 1KB-contiguous Wf runs (DRAM page locality)
// ---------------------------------------------------------------------------

typedef unsigned long long u64t;

// ------------------------- scratch (static device mem) ---------------------
__device__ __align__(16) float g_act[16 * 512 * 512];     // [b][l][h][dv]
__device__ __align__(16) float g_part[256 * 512 * 16];    // [ksplit][o][b]
__device__ __align__(16) __nv_bfloat16 g_xhi[3 * 8192 * 512];
__device__ __align__(16) __nv_bfloat16 g_xlo[3 * 8192 * 512];
__device__ __align__(16) __nv_bfloat16 g_whi[3 * 512 * 512];
__device__ __align__(16) __nv_bfloat16 g_wlo[3 * 512 * 512];
// head-major bf16 hi/lo projections: [h*16+b][l][64]
__device__ __align__(16) __nv_bfloat16 g_qBh[128 * 512 * 64];
__device__ __align__(16) __nv_bfloat16 g_qBl[128 * 512 * 64];
__device__ __align__(16) __nv_bfloat16 g_kBh[128 * 512 * 64];
__device__ __align__(16) __nv_bfloat16 g_kBl[128 * 512 * 64];
__device__ __align__(16) __nv_bfloat16 g_vBh[128 * 512 * 64];
__device__ __align__(16) __nv_bfloat16 g_vBl[128 * 512 * 64];

// ------------------------- f32x2 helpers (fc kernel) ------------------------
__device__ __forceinline__ u64t dup2(float x) {
    u64t r; asm("mov.b64 %0,{%1,%1};" : "=l"(r) : "f"(x)); return r;
}
__device__ __forceinline__ void fma2(u64t& d, u64t a, u64t b) {
    asm("fma.rn.f32x2 %0,%1,%2,%3;" : "=l"(d) : "l"(a), "l"(b), "l"(d));
}
__device__ __forceinline__ u64t add2(u64t a, u64t b) {
    u64t r; asm("add.rn.f32x2 %0,%1,%2;" : "=l"(r) : "l"(a), "l"(b)); return r;
}
__device__ __forceinline__ float2 unp2(u64t v) {
    float2 f; asm("mov.b64 {%0,%1},%2;" : "=f"(f.x), "=f"(f.y) : "l"(v)); return f;
}

// ------------------------- mma/ldmatrix/cp.async helpers --------------------
__device__ __forceinline__ uint32_t smem_u32(const void* p) {
    uint32_t a;
    asm("{ .reg .u64 t; cvta.to.shared.u64 t, %1; cvt.u32.u64 %0, t; }"
        : "=r"(a) : "l"(p));
    return a;
}
__device__ __forceinline__ void ldm4(uint32_t* r, uint32_t addr) {
    asm volatile("ldmatrix.sync.aligned.m8n8.x4.shared.b16 {%0,%1,%2,%3}, [%4];"
                 : "=r"(r[0]), "=r"(r[1]), "=r"(r[2]), "=r"(r[3]) : "r"(addr));
}
__device__ __forceinline__ void ldm2t(uint32_t* r, uint32_t addr) {
    asm volatile("ldmatrix.sync.aligned.m8n8.x4.trans.shared.b16 {%0,%1,%2,%3}, [%4];"
                 : "=r"(r[0]), "=r"(r[1]), "=r"(r[2]), "=r"(r[3]) : "r"(addr));
}
__device__ __forceinline__ void mma16816(float* c, const uint32_t* a,
                                         const uint32_t* b) {
    asm volatile(
        "mma.sync.aligned.m16n8k16.row.col.f32.bf16.bf16.f32 "
        "{%0,%1,%2,%3}, {%4,%5,%6,%7}, {%8,%9}, {%0,%1,%2,%3};"
        : "+f"(c[0]), "+f"(c[1]), "+f"(c[2]), "+f"(c[3])
        : "r"(a[0]), "r"(a[1]), "r"(a[2]), "r"(a[3]), "r"(b[0]), "r"(b[1]));
}
__device__ __forceinline__ void cpa16(uint32_t sa, const void* ga) {
    asm volatile("cp.async.cg.shared.global [%0], [%1], 16;"
                 :: "r"(sa), "l"(ga) : "memory");
}
__device__ __forceinline__ void cpa_commit() {
    asm volatile("cp.async.commit_group;" ::: "memory");
}
template <int N>
__device__ __forceinline__ void cpa_wait() {
    asm volatile("cp.async.wait_group %0;" :: "n"(N) : "memory");
}

// ===========================================================================
// cvt_kernel: fp32 -> (bf16 hi, bf16 lo) split for X (q,k,v) and W (Wq,Wk,Wv)
// ===========================================================================
__global__ void __launch_bounds__(256) cvt_kernel(
    const float* __restrict__ q, const float* __restrict__ k,
    const float* __restrict__ v,
    const float* __restrict__ Wq, const float* __restrict__ Wk,
    const float* __restrict__ Wv)
{
    const int t = blockIdx.x * 256 + threadIdx.x;
    const int XN4 = 3 * 1048576;
    const int WN4 = 3 * 65536;
    if (t >= XN4 + WN4) return;

    const float* src;
    __nv_bfloat16 *dh, *dl;
    size_t off4;
    if (t < XN4) {
        int z = t >> 20, i = t & 1048575;
        src = (z == 0) ? q : (z == 1) ? k : v;
        dh = g_xhi + (size_t)z * 4194304; dl = g_xlo + (size_t)z * 4194304;
        off4 = i;
    } else {
        int t2 = t - XN4;
        int z = t2 >> 16, i = t2 & 65535;
        src = (z == 0) ? Wq : (z == 1) ? Wk : Wv;
        dh = g_whi + (size_t)z * 262144; dl = g_wlo + (size_t)z * 262144;
        off4 = i;
    }
    float4 x = *(const float4*)(src + off4 * 4);
    float a[4] = { x.x, x.y, x.z, x.w };
    __nv_bfloat16 h[4], l[4];
#pragma unroll
    for (int j = 0; j < 4; j++) {
        h[j] = __float2bfloat16(a[j]);
        l[j] = __float2bfloat16(a[j] - __bfloat162float(h[j]));
    }
    __nv_bfloat162* ph = (__nv_bfloat162*)(dh + off4 * 4);
    __nv_bfloat162* pl = (__nv_bfloat162*)(dl + off4 * 4);
    ph[0] = __halves2bfloat162(h[0], h[1]); ph[1] = __halves2bfloat162(h[2], h[3]);
    pl[0] = __halves2bfloat162(l[0], l[1]); pl[1] = __halves2bfloat162(l[2], l[3]);
}

// ===========================================================================
// proj_mma: mma.sync bf16 split-2 GEMM. CTA tile M=128, N=128, K=512.
// Epilogue emits bf16 hi/lo head-major projections.
// ===========================================================================
#define RS     144
#define MHALF  18432
#define CH_BUF 73728
#define PJ_SMEM (2 * CH_BUF)

__global__ void __launch_bounds__(256) proj_mma(
    const float* __restrict__ bq, const float* __restrict__ bk,
    const float* __restrict__ bv)
{
    extern __shared__ char smem[];
    const uint32_t sb = smem_u32(smem);
    const int tid = threadIdx.x;
    const int wid = tid >> 5, lane = tid & 31;
    const int warp_m = wid & 3, warp_n = wid >> 2;

    const int z = blockIdx.z;
    const int m0 = blockIdx.y * 128;
    const int n0 = blockIdx.x * 128;
    const float* bias = (z == 0) ? bq : (z == 1) ? bk : bv;
    __nv_bfloat16* dH = (z == 0) ? g_qBh : (z == 1) ? g_kBh : g_vBh;
    __nv_bfloat16* dL = (z == 0) ? g_qBl : (z == 1) ? g_kBl : g_vBl;

    const __nv_bfloat16* gm[4] = {
        g_xhi + ((size_t)z * 8192 + m0) * 512,
        g_xlo + ((size_t)z * 8192 + m0) * 512,
        g_whi + ((size_t)z * 512 + n0) * 512,
        g_wlo + ((size_t)z * 512 + n0) * 512 };

    const uint32_t a_row  = lane & 15;
    const uint32_t a_koff = (lane >> 4) * 8;
    const uint32_t b_nrow = ((lane >> 4) * 8) + (lane & 7);
    const uint32_t b_koff = ((lane >> 3) & 1) * 8;

    float acc[2][8][4];
#pragma unroll
    for (int mt = 0; mt < 2; mt++)
#pragma unroll
        for (int nt = 0; nt < 8; nt++)
#pragma unroll
            for (int j = 0; j < 4; j++) acc[mt][nt][j] = 0.f;

    auto load_chunk = [&](int c) {
        const int kc = c * 64;
        const uint32_t base = sb + (uint32_t)(c & 1) * CH_BUF;
#pragma unroll
        for (int mat = 0; mat < 4; mat++) {
            const __nv_bfloat16* g = gm[mat];
#pragma unroll
            for (int i = 0; i < 4; i++) {
                int idx = tid + i * 256;
                int row = idx >> 3, seg = idx & 7;
                cpa16(base + mat * MHALF + row * RS + seg * 16,
                      g + (size_t)row * 512 + kc + seg * 8);
            }
        }
        cpa_commit();
    };

    load_chunk(0);
    load_chunk(1);

    for (int c = 0; c < 8; c++) {
        if (c < 7) cpa_wait<1>(); else cpa_wait<0>();
        __syncthreads();

        const uint32_t bufb = sb + (uint32_t)(c & 1) * CH_BUF;
        const uint32_t aBase = bufb + (warp_m * 32 + a_row) * RS + a_koff * 2;
        const uint32_t bBase = bufb + 2 * MHALF +
                               (warp_n * 64 + b_nrow) * RS + b_koff * 2;
#pragma unroll
        for (int ks = 0; ks < 4; ks++) {
            uint32_t aH[2][4], aL[2][4], bH[8][2], bL[8][2];
#pragma unroll
            for (int mt = 0; mt < 2; mt++) {
                uint32_t ad = aBase + mt * 16 * RS + ks * 32;
                ldm4(aH[mt], ad);
                ldm4(aL[mt], ad + MHALF);
            }
#pragma unroll
            for (int nb = 0; nb < 4; nb++) {
                uint32_t bd = bBase + nb * 16 * RS + ks * 32;
                uint32_t r[4];
                ldm4(r, bd);
                bH[2 * nb][0] = r[0]; bH[2 * nb][1] = r[1];
                bH[2 * nb + 1][0] = r[2]; bH[2 * nb + 1][1] = r[3];
                ldm4(r, bd + MHALF);
                bL[2 * nb][0] = r[0]; bL[2 * nb][1] = r[1];
                bL[2 * nb + 1][0] = r[2]; bL[2 * nb + 1][1] = r[3];
            }
#pragma unroll
            for (int mt = 0; mt < 2; mt++)
#pragma unroll
                for (int nt = 0; nt < 8; nt++) {
                    mma16816(acc[mt][nt], aH[mt], bH[nt]);
                    mma16816(acc[mt][nt], aH[mt], bL[nt]);
                    mma16816(acc[mt][nt], aL[mt], bH[nt]);
                }
        }
        __syncthreads();
        if (c + 2 < 8) load_chunk(c + 2);
    }

    // epilogue: regs -> smem stage (pad 132) -> bf16 hi/lo coalesced stores
    float* stage = (float*)smem;
#pragma unroll
    for (int mt = 0; mt < 2; mt++)
#pragma unroll
        for (int nt = 0; nt < 8; nt++) {
            int row = warp_m * 32 + mt * 16 + (lane >> 2);
            int col = warp_n * 64 + nt * 8 + (lane & 3) * 2;
            *(float2*)&stage[row * 132 + col] =
                make_float2(acc[mt][nt][0], acc[mt][nt][1]);
            *(float2*)&stage[(row + 8) * 132 + col] =
                make_float2(acc[mt][nt][2], acc[mt][nt][3]);
        }
    __syncthreads();

    for (int f = tid; f < 4096; f += 256) {
        int row = f >> 5, c4 = f & 31;
        int nn = c4 * 4;
        int rg = m0 + row, bbi = rg >> 9, ll = rg & 511;
        int hh2 = (n0 + nn) >> 6, d = nn & 63;
        float r[4];
#pragma unroll
        for (int j = 0; j < 4; j++)
            r[j] = stage[row * 132 + nn + j] + __ldg(&bias[n0 + nn + j]);
        __nv_bfloat16 h[4], l[4];
#pragma unroll
        for (int j = 0; j < 4; j++) {
            h[j] = __float2bfloat16(r[j]);
            l[j] = __float2bfloat16(r[j] - __bfloat162float(h[j]));
        }
        size_t off = (((size_t)hh2 * 16 + bbi) * 512 + ll) * 64 + d;
        __nv_bfloat162 hp0 = __halves2bfloat162(h[0], h[1]);
        __nv_bfloat162 hp1 = __halves2bfloat162(h[2], h[3]);
        __nv_bfloat162 lp0 = __halves2bfloat162(l[0], l[1]);
        __nv_bfloat162 lp1 = __halves2bfloat162(l[2], l[3]);
        uint2 uh, ul;
        uh.x = *(uint32_t*)&hp0; uh.y = *(uint32_t*)&hp1;
        ul.x = *(uint32_t*)&lp0; ul.y = *(uint32_t*)&lp1;
        *(uint2*)&dH[off] = uh;
        *(uint2*)&dL[off] = ul;
    }
}

// ===========================================================================
// attn v3 (R10): CTA per (hb, qtile 64), 512 threads, mma.sync both GEMMs.
// ===========================================================================
#define AQ   133120
#define AC   151552
#define AIVF 56320
#define ATTN2_SMEM 225536

__global__ void __launch_bounds__(512) attn_kernel(float* __restrict__ attn_out)
{
    extern __shared__ char smb[];
    float* smf = (float*)smb;
    const uint32_t sb = smem_u32(smb);
    const int tid = threadIdx.x;
    const int wid = tid >> 5, lane = tid & 31;
    const int hb = blockIdx.y;
    const int q0 = blockIdx.x * 64;
    const int bb = hb & 15, hh = hb >> 4;

    const __nv_bfloat16* kh = g_kBh + (size_t)hb * 512 * 64;
    const __nv_bfloat16* kl = g_kBl + (size_t)hb * 512 * 64;
    const __nv_bfloat16* vh = g_vBh + (size_t)hb * 512 * 64;
    const __nv_bfloat16* vl = g_vBl + (size_t)hb * 512 * 64;

    auto loadK = [&](int nt) {
        const uint32_t base = sb + AC + (uint32_t)(nt & 1) * 36864;
#pragma unroll
        for (int i = 0; i < 4; i++) {
            int f = tid + i * 512;
            int mat = f >> 10, idx = f & 1023;
            int rw = idx >> 3, sg = idx & 7;
            const __nv_bfloat16* g = mat ? kl : kh;
            cpa16(base + mat * 18432 + rw * 144 + sg * 16,
                  g + (size_t)(nt * 128 + rw) * 64 + sg * 8);
        }
    };
    auto loadV = [&](int nt) {
        const uint32_t base = sb + AC + 34816;
#pragma unroll
        for (int i = 0; i < 4; i++) {
            int f = tid + i * 512;
            int mat = f >> 10, idx = f & 1023;
            int rw = idx >> 3, sg = idx & 7;
            const __nv_bfloat16* g = mat ? vl : vh;
            cpa16(base + mat * 18432 + rw * 144 + sg * 16,
                  g + (size_t)(nt * 128 + rw) * 64 + sg * 8);
        }
    };

    {
        const __nv_bfloat16* qhp = g_qBh + ((size_t)hb * 512 + q0) * 64;
        const __nv_bfloat16* qlp = g_qBl + ((size_t)hb * 512 + q0) * 64;
#pragma unroll
        for (int i = 0; i < 2; i++) {
            int f = tid + i * 512;
            int mat = f >> 9, idx = f & 511;
            int rw = idx >> 3, sg = idx & 7;
            const __nv_bfloat16* g = mat ? qlp : qhp;
            cpa16(sb + AQ + mat * 9216 + rw * 144 + sg * 16,
                  g + (size_t)rw * 64 + sg * 8);
        }
        loadK(0); cpa_commit();
        loadK(1); cpa_commit();
    }

    // ---- Phase 1: S = QK^T / 8 via mma.  warp = (qb 0..3, nq 0..3) ----
    {
        const int qb = wid & 3, nq = wid >> 2;
        const uint32_t aAddr = sb + AQ +
            (uint32_t)((qb * 16 + (lane & 15)) * 144 + ((lane >> 4) * 8) * 2);
        cpa_wait<1>(); __syncthreads();
        uint32_t aH[4][4], aL[4][4];
#pragma unroll
        for (int ks = 0; ks < 4; ks++) {
            ldm4(aH[ks], aAddr + ks * 32);
            ldm4(aL[ks], aAddr + 9216 + ks * 32);
        }
        const uint32_t bOff = (uint32_t)(
            (nq * 32 + ((lane >> 4) * 8) + (lane & 7)) * 144 +
            (((lane >> 3) & 1) * 8) * 2);

        for (int nt = 0; nt < 4; nt++) {
            if (nt == 3) { cpa_wait<0>(); __syncthreads(); }
            else if (nt > 0) { cpa_wait<1>(); __syncthreads(); }
            const uint32_t Bb = sb + AC + (uint32_t)(nt & 1) * 36864 + bOff;
            float acc[4][4];
#pragma unroll
            for (int nb = 0; nb < 4; nb++)
#pragma unroll
                for (int j = 0; j < 4; j++) acc[nb][j] = 0.f;
#pragma unroll
            for (int ks = 0; ks < 4; ks++) {
                uint32_t bH[4][2], bL[4][2];
#pragma unroll
                for (int nb4 = 0; nb4 < 2; nb4++) {
                    uint32_t r[4];
                    ldm4(r, Bb + nb4 * 16 * 144 + ks * 32);
                    bH[2 * nb4][0] = r[0]; bH[2 * nb4][1] = r[1];
                    bH[2 * nb4 + 1][0] = r[2]; bH[2 * nb4 + 1][1] = r[3];
                    ldm4(r, Bb + 18432 + nb4 * 16 * 144 + ks * 32);
                    bL[2 * nb4][0] = r[0]; bL[2 * nb4][1] = r[1];
                    bL[2 * nb4 + 1][0] = r[2]; bL[2 * nb4 + 1][1] = r[3];
                }
#pragma unroll
                for (int nb = 0; nb < 4; nb++) mma16816(acc[nb], aH[ks], bH[nb]);
#pragma unroll
                for (int nb = 0; nb < 4; nb++) mma16816(acc[nb], aH[ks], bL[nb]);
#pragma unroll
                for (int nb = 0; nb < 4; nb++) mma16816(acc[nb], aL[ks], bH[nb]);
            }
            int row = qb * 16 + (lane >> 2);
#pragma unroll
            for (int nb = 0; nb < 4; nb++) {
                int col = nt * 128 + nq * 32 + nb * 8 + (lane & 3) * 2;
                *(float2*)&smf[row * 520 + col] =
                    make_float2(acc[nb][0] * 0.125f, acc[nb][1] * 0.125f);
                *(float2*)&smf[(row + 8) * 520 + col] =
                    make_float2(acc[nb][2] * 0.125f, acc[nb][3] * 0.125f);
            }
            __syncthreads();
            if (nt < 2) { loadK(nt + 2); cpa_commit(); }
        }
    }

    loadV(0); cpa_commit();

    // ---- Phase 2: softmax + attn writeback (16 warps x 4 rows) ----
    {
        for (int qi = 0; qi < 4; qi++) {
            int ql = wid * 4 + qi;
            float* srow = &smf[ql * 520];
            float m = -3.4e38f;
#pragma unroll
            for (int s = 0; s < 4; s++) {
                float4 v = *(const float4*)&srow[(s * 32 + lane) * 4];
                m = fmaxf(m, fmaxf(fmaxf(v.x, v.y), fmaxf(v.z, v.w)));
            }
#pragma unroll
            for (int off = 16; off >= 1; off >>= 1)
                m = fmaxf(m, __shfl_xor_sync(0xffffffffu, m, off));
            float sum = 0.f;
#pragma unroll
            for (int s = 0; s < 4; s++) {
                float4* p = (float4*)&srow[(s * 32 + lane) * 4];
                float4 v = *p;
                v.x = __expf(v.x - m); v.y = __expf(v.y - m);
                v.z = __expf(v.z - m); v.w = __expf(v.w - m);
                *p = v;
                sum += v.x + v.y + v.z + v.w;
            }
#pragma unroll
            for (int off = 16; off >= 1; off >>= 1)
                sum += __shfl_xor_sync(0xffffffffu, sum, off);
            float iv = 1.0f / sum;
            if (lane == 0) smf[AIVF + ql] = iv;
            float* drow = attn_out + ((size_t)hb * 512 + q0 + ql) * 512;
#pragma unroll
            for (int s = 0; s < 4; s++) {
                float4 v = *(const float4*)&srow[(s * 32 + lane) * 4];
                v.x *= iv; v.y *= iv; v.z *= iv; v.w *= iv;
                *(float4*)&drow[(s * 32 + lane) * 4] = v;
            }
        }
    }
    __syncthreads();

    // ---- Phase 3: O = P V via mma.  warp = (qb 0..3, dvh 0..3) ----
    {
        const int qb = wid & 3, dvh = wid >> 2;
        float oacc[2][4];
#pragma unroll
        for (int db = 0; db < 2; db++)
#pragma unroll
            for (int j = 0; j < 4; j++) oacc[db][j] = 0.f;

        const uint32_t pAddr = sb + AC +
            (uint32_t)((qb * 16 + (lane & 15)) * 272 + (lane >> 4) * 16);
        const uint32_t vAddr = sb + AC + 34816 +
            (uint32_t)((lane & 15) * 144 + ((lane >> 4) * 8 + dvh * 16) * 2);

        for (int nt = 0; nt < 4; nt++) {
#pragma unroll
            for (int it = 0; it < 4; it++) {
                int idx = tid + it * 512;
                int qq = idx >> 5, c4 = idx & 31;
                float4 s = *(const float4*)&smf[qq * 520 + nt * 128 + c4 * 4];
                float iv = smf[AIVF + qq];
                float p[4] = { s.x * iv, s.y * iv, s.z * iv, s.w * iv };
                __nv_bfloat16 h[4], l[4];
#pragma unroll
                for (int j = 0; j < 4; j++) {
                    h[j] = __float2bfloat16(p[j]);
                    l[j] = __float2bfloat16(p[j] - __bfloat162float(h[j]));
                }
                __nv_bfloat162 hp0 = __halves2bfloat162(h[0], h[1]);
                __nv_bfloat162 hp1 = __halves2bfloat162(h[2], h[3]);
                __nv_bfloat162 lp0 = __halves2bfloat162(l[0], l[1]);
                __nv_bfloat162 lp1 = __halves2bfloat162(l[2], l[3]);
                uint2 uh, ul;
                uh.x = *(uint32_t*)&hp0; uh.y = *(uint32_t*)&hp1;
                ul.x = *(uint32_t*)&lp0; ul.y = *(uint32_t*)&lp1;
                *(uint2*)(smb + AC + qq * 272 + c4 * 8) = uh;
                *(uint2*)(smb + AC + 17408 + qq * 272 + c4 * 8) = ul;
            }
            cpa_wait<0>(); __syncthreads();
#pragma unroll
            for (int ks = 0; ks < 8; ks++) {
                uint32_t pH[4], pL[4];
                ldm4(pH, pAddr + ks * 32);
                ldm4(pL, pAddr + 17408 + ks * 32);
                uint32_t vH[2][2], vL[2][2], r[4];
                ldm2t(r, vAddr + ks * 16 * 144);
                vH[0][0] = r[0]; vH[0][1] = r[1]; vH[1][0] = r[2]; vH[1][1] = r[3];
                ldm2t(r, vAddr + 18432 + ks * 16 * 144);
                vL[0][0] = r[0]; vL[0][1] = r[1]; vL[1][0] = r[2]; vL[1][1] = r[3];
#pragma unroll
                for (int db = 0; db < 2; db++) mma16816(oacc[db], pH, vH[db]);
#pragma unroll
                for (int db = 0; db < 2; db++) mma16816(oacc[db], pH, vL[db]);
#pragma unroll
                for (int db = 0; db < 2; db++) mma16816(oacc[db], pL, vH[db]);
            }
            __syncthreads();
            if (nt < 3) { loadV(nt + 1); cpa_commit(); }
        }

        int row = qb * 16 + (lane >> 2);
#pragma unroll
        for (int db = 0; db < 2; db++) {
            int dv = dvh * 16 + db * 8 + (lane & 3) * 2;
            *(float2*)&g_act[(((size_t)bb * 512 + q0 + row) * 8 + hh) * 64 + dv] =
                make_float2(oacc[db][0], oacc[db][1]);
            *(float2*)&g_act[(((size_t)bb * 512 + q0 + row + 8) * 8 + hh) * 64 + dv] =
                make_float2(oacc[db][2], oacc[db][3]);
        }
    }
}

// ===========================================================================
// FC v4: 512 threads, 64 o-rows/block, sub-chunk = 64 rows x 256 k (1KB
// contiguous per row), depth-2 ring. Same per-thread intensity as fc v3.
// smem: act 64KB + 2 x 64KB W ring = 192KB -> 1 block/SM, 16 warps.
// grid (256 ksplit, 8 oblocks).
// ===========================================================================
#define FC_KC 1024
#define FC_WCHUNK 65536                       // 64 rows x 256 k x 4B
#define FC_SMEM_BYTES (65536 + 2 * FC_WCHUNK) // 192 KB

__global__ void __launch_bounds__(512, 1) fc_kernel(const float* __restrict__ Wf)
{
    extern __shared__ char smc[];
    float2* sm2 = (float2*)smc;               // act [8 b2][1024] float2
    const float* wbufs = (const float*)(smc + 65536);
    const uint32_t sbW = smem_u32(smc + 65536);
    const int tid = threadIdx.x;
    const int k0 = blockIdx.x * FC_KC;
    const int o0 = blockIdx.y * 64;

    // W sub-chunk loader: 64 rows x 256 k fp32 = 64KB, ring slot sc&1.
    // Per row: 1KB contiguous (4 threads x 4 x 16B... 64 cp.async of 16B).
    auto loadW = [&](int sc) {
        const uint32_t base = sbW + (uint32_t)(sc & 1) * FC_WCHUNK;
        const float* src = Wf + (size_t)o0 * 262144 + k0 + sc * 256;
#pragma unroll
        for (int i = 0; i < 8; i++) {
            int c = tid + i * 512;               // 0..4095
            int row = c >> 6, sg = c & 63;       // 64 x 16B = 1KB per row
            cpa16(base + row * 1024 + sg * 16,
                  src + (size_t)row * 262144 + sg * 4);
        }
        cpa_commit();
    };
    loadW(0); loadW(1);

    // stage act with XOR swizzle (overlaps in-flight cp.async)
    const float4* act4 = (const float4*)g_act;
    float* smf = (float*)sm2;
    for (int f = tid; f < 4096; f += 512) {
        int b = f >> 8, c = f & 255;
        float4 v = act4[(size_t)b * 65536 + (k0 >> 2) + c];
        int b2 = b >> 1, lo = b & 1;
        int cx = (c >> 2) & 3;
        int base = b2 * FC_KC + c * 4;
        smf[2 * (base + (0 ^ cx)) + lo] = v.x;
        smf[2 * (base + (1 ^ cx)) + lo] = v.y;
        smf[2 * (base + (2 ^ cx)) + lo] = v.z;
        smf[2 * (base + (3 ^ cx)) + lo] = v.w;
    }

    const int warp = tid >> 5, lane = tid & 31;
    const int ob = warp * 4;                  // 16 warps x 4 = 64 outputs
    const int xv = (lane >> 2) & 3;

    u64t acc[4][8];
#pragma unroll
    for (int j = 0; j < 4; j++)
#pragma unroll
        for (int b2 = 0; b2 < 8; b2++) acc[j][b2] = 0ull;

    for (int sc = 0; sc < 4; sc++) {
        if (sc < 3) cpa_wait<1>(); else cpa_wait<0>();
        __syncthreads();                      // also covers act staging at sc=0

        const float* wb = wbufs + (size_t)(sc & 1) * 16384;   // 16384 floats
#pragma unroll
        for (int it = 0; it < 2; it++) {
            const int ik0 = it * 128 + lane * 4;              // 0..255 k-sub
            float wv[4][4];
#pragma unroll
            for (int j = 0; j < 4; j++) {
                float4 w4 = *(const float4*)&wb[(ob + j) * 256 + ik0];
                wv[j][0] = w4.x; wv[j][1] = w4.y; wv[j][2] = w4.z; wv[j][3] = w4.w;
            }
            const int i0 = sc * 256 + ik0;    // global k in 1024; (i0>>4)&3==xv
#pragma unroll
            for (int kk = 0; kk < 4; kk++) {
                const int ik = i0 + (kk ^ xv);
                u64t a[8];
#pragma unroll
                for (int b2 = 0; b2 < 8; b2++)
                    a[b2] = *(const u64t*)&sm2[b2 * FC_KC + ik];
#pragma unroll
                for (int j = 0; j < 4; j++) {
                    u64t wd = dup2(wv[j][kk]);
#pragma unroll
                    for (int b2 = 0; b2 < 8; b2++)
                        fma2(acc[j][b2], wd, a[b2]);
                }
            }
        }
        __syncthreads();                      // all warps done with slot sc&1
        if (sc + 2 < 4) loadW(sc + 2);
    }

#pragma unroll
    for (int j = 0; j < 4; j++)
#pragma unroll
        for (int b2 = 0; b2 < 8; b2++) {
#pragma unroll
            for (int off = 16; off >= 1; off >>= 1) {
                u64t o = __shfl_down_sync(0xffffffffu, acc[j][b2], off);
                acc[j][b2] = add2(acc[j][b2], o);
            }
        }
    if (lane == 0) {
#pragma unroll
        for (int j = 0; j < 4; j++) {
            size_t base = ((size_t)blockIdx.x * 512 + o0 + ob + j) * 16;
#pragma unroll
            for (int b2 = 0; b2 < 8; b2++) {
                float2 f = unp2(acc[j][b2]);
                g_part[base + 2 * b2]     = f.x;
                g_part[base + 2 * b2 + 1] = f.y;
            }
        }
    }
}

__global__ void __launch_bounds__(256) reduce_fc(const float* __restrict__ bf,
                                                 float* __restrict__ out)
{
    __shared__ float red[8][33];
    const int t = threadIdx.x;
    const int oi = blockIdx.x * 32 + (t & 31);
    const int part = t >> 5;
    const int o = oi >> 4, b = oi & 15;
    float s = 0.f;
#pragma unroll 8
    for (int ks = part * 32; ks < part * 32 + 32; ks++)
        s += g_part[((size_t)ks * 512 + o) * 16 + b];
    red[part][t & 31] = s;
    __syncthreads();
    if (t < 32) {
        float tot = 0.f;
#pragma unroll
        for (int j = 0; j < 8; j++) tot += red[j][t];
        int oo = blockIdx.x * 32 + t;
        out[(oo & 15) * 512 + (oo >> 4)] = tot + bf[oo >> 4];
    }
}

// ===========================================================================
extern "C" void kernel_launch(void* const* d_in, const int* in_sizes, int n_in,
                              void* d_out, int out_size)
{
    const float* q  = (const float*)d_in[0];
    const float* k  = (const float*)d_in[1];
    const float* v  = (const float*)d_in[2];
    const float* Wq = (const float*)d_in[3];
    const float* bq = (const float*)d_in[4];
    const float* Wk = (const float*)d_in[5];
    const float* bk = (const float*)d_in[6];
    const float* Wv = (const float*)d_in[7];
    const float* bv = (const float*)d_in[8];
    const float* Wf = (const float*)d_in[9];
    const float* bf = (const float*)d_in[10];
    float* out = (float*)d_out;

    cudaFuncSetAttribute(proj_mma, cudaFuncAttributeMaxDynamicSharedMemorySize, PJ_SMEM);
    cudaFuncSetAttribute(attn_kernel, cudaFuncAttributeMaxDynamicSharedMemorySize,
                         ATTN2_SMEM);
    cudaFuncSetAttribute(fc_kernel, cudaFuncAttributeMaxDynamicSharedMemorySize,
                         FC_SMEM_BYTES);

    cvt_kernel<<<13056, 256>>>(q, k, v, Wq, Wk, Wv);
    proj_mma<<<dim3(4, 64, 3), 256, PJ_SMEM>>>(bq, bk, bv);
    attn_kernel<<<dim3(8, 128), 512, ATTN2_SMEM>>>(out + 8192);
    fc_kernel<<<dim3(256, 8), 512, FC_SMEM_BYTES>>>(Wf);
    reduce_fc<<<256, 256>>>(bf, out);
}

// round 13
// speedup vs baseline: 1.0756x; 1.0756x over previous
#include <cuda_runtime.h>
#include <cuda_bf16.h>
#include <cstdint>

// ---------------------------------------------------------------------------
// MultiHeadAttention: B=16, L=512, D=512, H=8, DK=DV=64, TEMP=8
// out = ( output[16,512], attn[128,512,512] ) concatenated in d_out (fp32)
// R12: fc reverted to v3 (192us proven); proj K-chunk 32 -> 2 CTAs/SM
// ---------------------------------------------------------------------------

typedef unsigned long long u64t;

// ------------------------- scratch (static device mem) ---------------------
__device__ __align__(16) float g_act[16 * 512 * 512];     // [b][l][h][dv]
__device__ __align__(16) float g_part[256 * 512 * 16];    // [ksplit][o][b]
__device__ __align__(16) __nv_bfloat16 g_xhi[3 * 8192 * 512];
__device__ __align__(16) __nv_bfloat16 g_xlo[3 * 8192 * 512];
__device__ __align__(16) __nv_bfloat16 g_whi[3 * 512 * 512];
__device__ __align__(16) __nv_bfloat16 g_wlo[3 * 512 * 512];
// head-major bf16 hi/lo projections: [h*16+b][l][64]
__device__ __align__(16) __nv_bfloat16 g_qBh[128 * 512 * 64];
__device__ __align__(16) __nv_bfloat16 g_qBl[128 * 512 * 64];
__device__ __align__(16) __nv_bfloat16 g_kBh[128 * 512 * 64];
__device__ __align__(16) __nv_bfloat16 g_kBl[128 * 512 * 64];
__device__ __align__(16) __nv_bfloat16 g_vBh[128 * 512 * 64];
__device__ __align__(16) __nv_bfloat16 g_vBl[128 * 512 * 64];

// ------------------------- f32x2 helpers (fc kernel) ------------------------
__device__ __forceinline__ u64t dup2(float x) {
    u64t r; asm("mov.b64 %0,{%1,%1};" : "=l"(r) : "f"(x)); return r;
}
__device__ __forceinline__ void fma2(u64t& d, u64t a, u64t b) {
    asm("fma.rn.f32x2 %0,%1,%2,%3;" : "=l"(d) : "l"(a), "l"(b), "l"(d));
}
__device__ __forceinline__ u64t add2(u64t a, u64t b) {
    u64t r; asm("add.rn.f32x2 %0,%1,%2;" : "=l"(r) : "l"(a), "l"(b)); return r;
}
__device__ __forceinline__ float2 unp2(u64t v) {
    float2 f; asm("mov.b64 {%0,%1},%2;" : "=f"(f.x), "=f"(f.y) : "l"(v)); return f;
}

// ------------------------- mma/ldmatrix/cp.async helpers --------------------
__device__ __forceinline__ uint32_t smem_u32(const void* p) {
    uint32_t a;
    asm("{ .reg .u64 t; cvta.to.shared.u64 t, %1; cvt.u32.u64 %0, t; }"
        : "=r"(a) : "l"(p));
    return a;
}
__device__ __forceinline__ void ldm4(uint32_t* r, uint32_t addr) {
    asm volatile("ldmatrix.sync.aligned.m8n8.x4.shared.b16 {%0,%1,%2,%3}, [%4];"
                 : "=r"(r[0]), "=r"(r[1]), "=r"(r[2]), "=r"(r[3]) : "r"(addr));
}
__device__ __forceinline__ void ldm2t(uint32_t* r, uint32_t addr) {
    asm volatile("ldmatrix.sync.aligned.m8n8.x4.trans.shared.b16 {%0,%1,%2,%3}, [%4];"
                 : "=r"(r[0]), "=r"(r[1]), "=r"(r[2]), "=r"(r[3]) : "r"(addr));
}
__device__ __forceinline__ void mma16816(float* c, const uint32_t* a,
                                         const uint32_t* b) {
    asm volatile(
        "mma.sync.aligned.m16n8k16.row.col.f32.bf16.bf16.f32 "
        "{%0,%1,%2,%3}, {%4,%5,%6,%7}, {%8,%9}, {%0,%1,%2,%3};"
        : "+f"(c[0]), "+f"(c[1]), "+f"(c[2]), "+f"(c[3])
        : "r"(a[0]), "r"(a[1]), "r"(a[2]), "r"(a[3]), "r"(b[0]), "r"(b[1]));
}
__device__ __forceinline__ void cpa16(uint32_t sa, const void* ga) {
    asm volatile("cp.async.cg.shared.global [%0], [%1], 16;"
                 :: "r"(sa), "l"(ga) : "memory");
}
__device__ __forceinline__ void cpa_commit() {
    asm volatile("cp.async.commit_group;" ::: "memory");
}
template <int N>
__device__ __forceinline__ void cpa_wait() {
    asm volatile("cp.async.wait_group %0;" :: "n"(N) : "memory");
}

// ===========================================================================
// cvt_kernel: fp32 -> (bf16 hi, bf16 lo) split for X (q,k,v) and W (Wq,Wk,Wv)
// ===========================================================================
__global__ void __launch_bounds__(256) cvt_kernel(
    const float* __restrict__ q, const float* __restrict__ k,
    const float* __restrict__ v,
    const float* __restrict__ Wq, const float* __restrict__ Wk,
    const float* __restrict__ Wv)
{
    const int t = blockIdx.x * 256 + threadIdx.x;
    const int XN4 = 3 * 1048576;
    const int WN4 = 3 * 65536;
    if (t >= XN4 + WN4) return;

    const float* src;
    __nv_bfloat16 *dh, *dl;
    size_t off4;
    if (t < XN4) {
        int z = t >> 20, i = t & 1048575;
        src = (z == 0) ? q : (z == 1) ? k : v;
        dh = g_xhi + (size_t)z * 4194304; dl = g_xlo + (size_t)z * 4194304;
        off4 = i;
    } else {
        int t2 = t - XN4;
        int z = t2 >> 16, i = t2 & 65535;
        src = (z == 0) ? Wq : (z == 1) ? Wk : Wv;
        dh = g_whi + (size_t)z * 262144; dl = g_wlo + (size_t)z * 262144;
        off4 = i;
    }
    float4 x = *(const float4*)(src + off4 * 4);
    float a[4] = { x.x, x.y, x.z, x.w };
    __nv_bfloat16 h[4], l[4];
#pragma unroll
    for (int j = 0; j < 4; j++) {
        h[j] = __float2bfloat16(a[j]);
        l[j] = __float2bfloat16(a[j] - __bfloat162float(h[j]));
    }
    __nv_bfloat162* ph = (__nv_bfloat162*)(dh + off4 * 4);
    __nv_bfloat162* pl = (__nv_bfloat162*)(dl + off4 * 4);
    ph[0] = __halves2bfloat162(h[0], h[1]); ph[1] = __halves2bfloat162(h[2], h[3]);
    pl[0] = __halves2bfloat162(l[0], l[1]); pl[1] = __halves2bfloat162(l[2], l[3]);
}

// ===========================================================================
// proj_mma v2: K-chunk 32, double-buffered -> 80KB smem -> 2 CTAs/SM.
// Rows 32 bf16 = 64B, padded stride 80B (conflict-free for ldm4).
// ===========================================================================
#define RS2    80
#define MHALF2 10240               // 128 rows x 80 B
#define CH_BUF2 40960              // A_hi + A_lo + B_hi + B_lo
#define PJ_SMEM (2 * CH_BUF2)      // 81920

__global__ void __launch_bounds__(256, 2) proj_mma(
    const float* __restrict__ bq, const float* __restrict__ bk,
    const float* __restrict__ bv)
{
    extern __shared__ char smem[];
    const uint32_t sb = smem_u32(smem);
    const int tid = threadIdx.x;
    const int wid = tid >> 5, lane = tid & 31;
    const int warp_m = wid & 3, warp_n = wid >> 2;

    const int z = blockIdx.z;
    const int m0 = blockIdx.y * 128;
    const int n0 = blockIdx.x * 128;
    const float* bias = (z == 0) ? bq : (z == 1) ? bk : bv;
    __nv_bfloat16* dH = (z == 0) ? g_qBh : (z == 1) ? g_kBh : g_vBh;
    __nv_bfloat16* dL = (z == 0) ? g_qBl : (z == 1) ? g_kBl : g_vBl;

    const __nv_bfloat16* gm[4] = {
        g_xhi + ((size_t)z * 8192 + m0) * 512,
        g_xlo + ((size_t)z * 8192 + m0) * 512,
        g_whi + ((size_t)z * 512 + n0) * 512,
        g_wlo + ((size_t)z * 512 + n0) * 512 };

    const uint32_t a_row  = lane & 15;
    const uint32_t a_koff = (lane >> 4) * 16;          // bytes
    const uint32_t b_nrow = ((lane >> 4) * 8) + (lane & 7);
    const uint32_t b_koff = ((lane >> 3) & 1) * 16;    // bytes

    float acc[2][8][4];
#pragma unroll
    for (int mt = 0; mt < 2; mt++)
#pragma unroll
        for (int nt = 0; nt < 8; nt++)
#pragma unroll
            for (int j = 0; j < 4; j++) acc[mt][nt][j] = 0.f;

    // chunk = 32 k. Loads: 4 mats x 128 rows x 4 segs(16B) = 2048 cpa16.
    auto load_chunk = [&](int c) {
        const int kc = c * 32;
        const uint32_t base = sb + (uint32_t)(c & 1) * CH_BUF2;
#pragma unroll
        for (int i = 0; i < 8; i++) {
            int idx = tid + i * 256;                   // 0..2047
            int mat = idx >> 9, r2 = idx & 511;
            int row = r2 >> 2, seg = r2 & 3;
            cpa16(base + mat * MHALF2 + row * RS2 + seg * 16,
                  gm[mat] + (size_t)row * 512 + kc + seg * 8);
        }
        cpa_commit();
    };

    load_chunk(0);
    load_chunk(1);

    for (int c = 0; c < 16; c++) {
        if (c < 15) cpa_wait<1>(); else cpa_wait<0>();
        __syncthreads();

        const uint32_t bufb = sb + (uint32_t)(c & 1) * CH_BUF2;
        const uint32_t aBase = bufb + (warp_m * 32 + a_row) * RS2 + a_koff;
        const uint32_t bBase = bufb + 2 * MHALF2 +
                               (warp_n * 64 + b_nrow) * RS2 + b_koff;
#pragma unroll
        for (int ks = 0; ks < 2; ks++) {
            uint32_t aH[2][4], aL[2][4], bH[8][2], bL[8][2];
#pragma unroll
            for (int mt = 0; mt < 2; mt++) {
                uint32_t ad = aBase + mt * 16 * RS2 + ks * 32;
                ldm4(aH[mt], ad);
                ldm4(aL[mt], ad + MHALF2);
            }
#pragma unroll
            for (int nb = 0; nb < 4; nb++) {
                uint32_t bd = bBase + nb * 16 * RS2 + ks * 32;
                uint32_t r[4];
                ldm4(r, bd);
                bH[2 * nb][0] = r[0]; bH[2 * nb][1] = r[1];
                bH[2 * nb + 1][0] = r[2]; bH[2 * nb + 1][1] = r[3];
                ldm4(r, bd + MHALF2);
                bL[2 * nb][0] = r[0]; bL[2 * nb][1] = r[1];
                bL[2 * nb + 1][0] = r[2]; bL[2 * nb + 1][1] = r[3];
            }
#pragma unroll
            for (int mt = 0; mt < 2; mt++)
#pragma unroll
                for (int nt = 0; nt < 8; nt++) {
                    mma16816(acc[mt][nt], aH[mt], bH[nt]);
                    mma16816(acc[mt][nt], aH[mt], bL[nt]);
                    mma16816(acc[mt][nt], aL[mt], bH[nt]);
                }
        }
        __syncthreads();
        if (c + 2 < 16) load_chunk(c + 2);
    }

    // epilogue: regs -> smem stage (pad 132) -> bf16 hi/lo coalesced stores
    float* stage = (float*)smem;
#pragma unroll
    for (int mt = 0; mt < 2; mt++)
#pragma unroll
        for (int nt = 0; nt < 8; nt++) {
            int row = warp_m * 32 + mt * 16 + (lane >> 2);
            int col = warp_n * 64 + nt * 8 + (lane & 3) * 2;
            *(float2*)&stage[row * 132 + col] =
                make_float2(acc[mt][nt][0], acc[mt][nt][1]);
            *(float2*)&stage[(row + 8) * 132 + col] =
                make_float2(acc[mt][nt][2], acc[mt][nt][3]);
        }
    __syncthreads();

    for (int f = tid; f < 4096; f += 256) {
        int row = f >> 5, c4 = f & 31;
        int nn = c4 * 4;
        int rg = m0 + row, bbi = rg >> 9, ll = rg & 511;
        int hh2 = (n0 + nn) >> 6, d = nn & 63;
        float r[4];
#pragma unroll
        for (int j = 0; j < 4; j++)
            r[j] = stage[row * 132 + nn + j] + __ldg(&bias[n0 + nn + j]);
        __nv_bfloat16 h[4], l[4];
#pragma unroll
        for (int j = 0; j < 4; j++) {
            h[j] = __float2bfloat16(r[j]);
            l[j] = __float2bfloat16(r[j] - __bfloat162float(h[j]));
        }
        size_t off = (((size_t)hh2 * 16 + bbi) * 512 + ll) * 64 + d;
        __nv_bfloat162 hp0 = __halves2bfloat162(h[0], h[1]);
        __nv_bfloat162 hp1 = __halves2bfloat162(h[2], h[3]);
        __nv_bfloat162 lp0 = __halves2bfloat162(l[0], l[1]);
        __nv_bfloat162 lp1 = __halves2bfloat162(l[2], l[3]);
        uint2 uh, ul;
        uh.x = *(uint32_t*)&hp0; uh.y = *(uint32_t*)&hp1;
        ul.x = *(uint32_t*)&lp0; ul.y = *(uint32_t*)&lp1;
        *(uint2*)&dH[off] = uh;
        *(uint2*)&dL[off] = ul;
    }
}

// ===========================================================================
// attn v3 (R10): CTA per (hb, qtile 64), 512 threads, mma.sync both GEMMs.
// ===========================================================================
#define AQ   133120
#define AC   151552
#define AIVF 56320
#define ATTN2_SMEM 225536

__global__ void __launch_bounds__(512) attn_kernel(float* __restrict__ attn_out)
{
    extern __shared__ char smb[];
    float* smf = (float*)smb;
    const uint32_t sb = smem_u32(smb);
    const int tid = threadIdx.x;
    const int wid = tid >> 5, lane = tid & 31;
    const int hb = blockIdx.y;
    const int q0 = blockIdx.x * 64;
    const int bb = hb & 15, hh = hb >> 4;

    const __nv_bfloat16* kh = g_kBh + (size_t)hb * 512 * 64;
    const __nv_bfloat16* kl = g_kBl + (size_t)hb * 512 * 64;
    const __nv_bfloat16* vh = g_vBh + (size_t)hb * 512 * 64;
    const __nv_bfloat16* vl = g_vBl + (size_t)hb * 512 * 64;

    auto loadK = [&](int nt) {
        const uint32_t base = sb + AC + (uint32_t)(nt & 1) * 36864;
#pragma unroll
        for (int i = 0; i < 4; i++) {
            int f = tid + i * 512;
            int mat = f >> 10, idx = f & 1023;
            int rw = idx >> 3, sg = idx & 7;
            const __nv_bfloat16* g = mat ? kl : kh;
            cpa16(base + mat * 18432 + rw * 144 + sg * 16,
                  g + (size_t)(nt * 128 + rw) * 64 + sg * 8);
        }
    };
    auto loadV = [&](int nt) {
        const uint32_t base = sb + AC + 34816;
#pragma unroll
        for (int i = 0; i < 4; i++) {
            int f = tid + i * 512;
            int mat = f >> 10, idx = f & 1023;
            int rw = idx >> 3, sg = idx & 7;
            const __nv_bfloat16* g = mat ? vl : vh;
            cpa16(base + mat * 18432 + rw * 144 + sg * 16,
                  g + (size_t)(nt * 128 + rw) * 64 + sg * 8);
        }
    };

    {
        const __nv_bfloat16* qhp = g_qBh + ((size_t)hb * 512 + q0) * 64;
        const __nv_bfloat16* qlp = g_qBl + ((size_t)hb * 512 + q0) * 64;
#pragma unroll
        for (int i = 0; i < 2; i++) {
            int f = tid + i * 512;
            int mat = f >> 9, idx = f & 511;
            int rw = idx >> 3, sg = idx & 7;
            const __nv_bfloat16* g = mat ? qlp : qhp;
            cpa16(sb + AQ + mat * 9216 + rw * 144 + sg * 16,
                  g + (size_t)rw * 64 + sg * 8);
        }
        loadK(0); cpa_commit();
        loadK(1); cpa_commit();
    }

    // ---- Phase 1: S = QK^T / 8 via mma.  warp = (qb 0..3, nq 0..3) ----
    {
        const int qb = wid & 3, nq = wid >> 2;
        const uint32_t aAddr = sb + AQ +
            (uint32_t)((qb * 16 + (lane & 15)) * 144 + ((lane >> 4) * 8) * 2);
        cpa_wait<1>(); __syncthreads();
        uint32_t aH[4][4], aL[4][4];
#pragma unroll
        for (int ks = 0; ks < 4; ks++) {
            ldm4(aH[ks], aAddr + ks * 32);
            ldm4(aL[ks], aAddr + 9216 + ks * 32);
        }
        const uint32_t bOff = (uint32_t)(
            (nq * 32 + ((lane >> 4) * 8) + (lane & 7)) * 144 +
            (((lane >> 3) & 1) * 8) * 2);

        for (int nt = 0; nt < 4; nt++) {
            if (nt == 3) { cpa_wait<0>(); __syncthreads(); }
            else if (nt > 0) { cpa_wait<1>(); __syncthreads(); }
            const uint32_t Bb = sb + AC + (uint32_t)(nt & 1) * 36864 + bOff;
            float acc[4][4];
#pragma unroll
            for (int nb = 0; nb < 4; nb++)
#pragma unroll
                for (int j = 0; j < 4; j++) acc[nb][j] = 0.f;
#pragma unroll
            for (int ks = 0; ks < 4; ks++) {
                uint32_t bH[4][2], bL[4][2];
#pragma unroll
                for (int nb4 = 0; nb4 < 2; nb4++) {
                    uint32_t r[4];
                    ldm4(r, Bb + nb4 * 16 * 144 + ks * 32);
                    bH[2 * nb4][0] = r[0]; bH[2 * nb4][1] = r[1];
                    bH[2 * nb4 + 1][0] = r[2]; bH[2 * nb4 + 1][1] = r[3];
                    ldm4(r, Bb + 18432 + nb4 * 16 * 144 + ks * 32);
                    bL[2 * nb4][0] = r[0]; bL[2 * nb4][1] = r[1];
                    bL[2 * nb4 + 1][0] = r[2]; bL[2 * nb4 + 1][1] = r[3];
                }
#pragma unroll
                for (int nb = 0; nb < 4; nb++) mma16816(acc[nb], aH[ks], bH[nb]);
#pragma unroll
                for (int nb = 0; nb < 4; nb++) mma16816(acc[nb], aH[ks], bL[nb]);
#pragma unroll
                for (int nb = 0; nb < 4; nb++) mma16816(acc[nb], aL[ks], bH[nb]);
            }
            int row = qb * 16 + (lane >> 2);
#pragma unroll
            for (int nb = 0; nb < 4; nb++) {
                int col = nt * 128 + nq * 32 + nb * 8 + (lane & 3) * 2;
                *(float2*)&smf[row * 520 + col] =
                    make_float2(acc[nb][0] * 0.125f, acc[nb][1] * 0.125f);
                *(float2*)&smf[(row + 8) * 520 + col] =
                    make_float2(acc[nb][2] * 0.125f, acc[nb][3] * 0.125f);
            }
            __syncthreads();
            if (nt < 2) { loadK(nt + 2); cpa_commit(); }
        }
    }

    loadV(0); cpa_commit();

    // ---- Phase 2: softmax + attn writeback (16 warps x 4 rows) ----
    {
        for (int qi = 0; qi < 4; qi++) {
            int ql = wid * 4 + qi;
            float* srow = &smf[ql * 520];
            float m = -3.4e38f;
#pragma unroll
            for (int s = 0; s < 4; s++) {
                float4 v = *(const float4*)&srow[(s * 32 + lane) * 4];
                m = fmaxf(m, fmaxf(fmaxf(v.x, v.y), fmaxf(v.z, v.w)));
            }
#pragma unroll
            for (int off = 16; off >= 1; off >>= 1)
                m = fmaxf(m, __shfl_xor_sync(0xffffffffu, m, off));
            float sum = 0.f;
#pragma unroll
            for (int s = 0; s < 4; s++) {
                float4* p = (float4*)&srow[(s * 32 + lane) * 4];
                float4 v = *p;
                v.x = __expf(v.x - m); v.y = __expf(v.y - m);
                v.z = __expf(v.z - m); v.w = __expf(v.w - m);
                *p = v;
                sum += v.x + v.y + v.z + v.w;
            }
#pragma unroll
            for (int off = 16; off >= 1; off >>= 1)
                sum += __shfl_xor_sync(0xffffffffu, sum, off);
            float iv = 1.0f / sum;
            if (lane == 0) smf[AIVF + ql] = iv;
            float* drow = attn_out + ((size_t)hb * 512 + q0 + ql) * 512;
#pragma unroll
            for (int s = 0; s < 4; s++) {
                float4 v = *(const float4*)&srow[(s * 32 + lane) * 4];
                v.x *= iv; v.y *= iv; v.z *= iv; v.w *= iv;
                *(float4*)&drow[(s * 32 + lane) * 4] = v;
            }
        }
    }
    __syncthreads();

    // ---- Phase 3: O = P V via mma.  warp = (qb 0..3, dvh 0..3) ----
    {
        const int qb = wid & 3, dvh = wid >> 2;
        float oacc[2][4];
#pragma unroll
        for (int db = 0; db < 2; db++)
#pragma unroll
            for (int j = 0; j < 4; j++) oacc[db][j] = 0.f;

        const uint32_t pAddr = sb + AC +
            (uint32_t)((qb * 16 + (lane & 15)) * 272 + (lane >> 4) * 16);
        const uint32_t vAddr = sb + AC + 34816 +
            (uint32_t)((lane & 15) * 144 + ((lane >> 4) * 8 + dvh * 16) * 2);

        for (int nt = 0; nt < 4; nt++) {
#pragma unroll
            for (int it = 0; it < 4; it++) {
                int idx = tid + it * 512;
                int qq = idx >> 5, c4 = idx & 31;
                float4 s = *(const float4*)&smf[qq * 520 + nt * 128 + c4 * 4];
                float iv = smf[AIVF + qq];
                float p[4] = { s.x * iv, s.y * iv, s.z * iv, s.w * iv };
                __nv_bfloat16 h[4], l[4];
#pragma unroll
                for (int j = 0; j < 4; j++) {
                    h[j] = __float2bfloat16(p[j]);
                    l[j] = __float2bfloat16(p[j] - __bfloat162float(h[j]));
                }
                __nv_bfloat162 hp0 = __halves2bfloat162(h[0], h[1]);
                __nv_bfloat162 hp1 = __halves2bfloat162(h[2], h[3]);
                __nv_bfloat162 lp0 = __halves2bfloat162(l[0], l[1]);
                __nv_bfloat162 lp1 = __halves2bfloat162(l[2], l[3]);
                uint2 uh, ul;
                uh.x = *(uint32_t*)&hp0; uh.y = *(uint32_t*)&hp1;
                ul.x = *(uint32_t*)&lp0; ul.y = *(uint32_t*)&lp1;
                *(uint2*)(smb + AC + qq * 272 + c4 * 8) = uh;
                *(uint2*)(smb + AC + 17408 + qq * 272 + c4 * 8) = ul;
            }
            cpa_wait<0>(); __syncthreads();
#pragma unroll
            for (int ks = 0; ks < 8; ks++) {
                uint32_t pH[4], pL[4];
                ldm4(pH, pAddr + ks * 32);
                ldm4(pL, pAddr + 17408 + ks * 32);
                uint32_t vH[2][2], vL[2][2], r[4];
                ldm2t(r, vAddr + ks * 16 * 144);
                vH[0][0] = r[0]; vH[0][1] = r[1]; vH[1][0] = r[2]; vH[1][1] = r[3];
                ldm2t(r, vAddr + 18432 + ks * 16 * 144);
                vL[0][0] = r[0]; vL[0][1] = r[1]; vL[1][0] = r[2]; vL[1][1] = r[3];
#pragma unroll
                for (int db = 0; db < 2; db++) mma16816(oacc[db], pH, vH[db]);
#pragma unroll
                for (int db = 0; db < 2; db++) mma16816(oacc[db], pH, vL[db]);
#pragma unroll
                for (int db = 0; db < 2; db++) mma16816(oacc[db], pL, vH[db]);
            }
            __syncthreads();
            if (nt < 3) { loadV(nt + 1); cpa_commit(); }
        }

        int row = qb * 16 + (lane >> 2);
#pragma unroll
        for (int db = 0; db < 2; db++) {
            int dv = dvh * 16 + db * 8 + (lane & 3) * 2;
            *(float2*)&g_act[(((size_t)bb * 512 + q0 + row) * 8 + hh) * 64 + dv] =
                make_float2(oacc[db][0], oacc[db][1]);
            *(float2*)&g_act[(((size_t)bb * 512 + q0 + row + 8) * 8 + hh) * 64 + dv] =
                make_float2(oacc[db][2], oacc[db][3]);
        }
    }
}

// ===========================================================================
// FC v3 (192us proven): 4 o/warp + cp.async Wf ring, 256 thr, 2 blocks/SM.
// ===========================================================================
#define FC_KC 1024
#define FC_SMEM_BYTES (65536 + 3 * 16384)    // 112 KB

__global__ void __launch_bounds__(256, 2) fc_kernel(const float* __restrict__ Wf)
{
    extern __shared__ char smc[];
    float2* sm2 = (float2*)smc;
    const float* wbufs = (const float*)(smc + 65536);
    const uint32_t sbW = smem_u32(smc + 65536);
    const int tid = threadIdx.x;
    const int k0 = blockIdx.x * FC_KC;
    const int o0 = blockIdx.y * 32;

    auto loadW = [&](int sc) {
        const uint32_t base = sbW + (uint32_t)(sc % 3) * 16384;
        const float* src = Wf + (size_t)o0 * 262144 + k0 + sc * 128;
#pragma unroll
        for (int i = 0; i < 4; i++) {
            int c = tid + i * 256;
            int row = c >> 5, sg = c & 31;
            cpa16(base + row * 512 + sg * 16,
                  src + (size_t)row * 262144 + sg * 4);
        }
        cpa_commit();
    };
    loadW(0); loadW(1); loadW(2);

    const float4* act4 = (const float4*)g_act;
    float* smf = (float*)sm2;
    for (int f = tid; f < 4096; f += 256) {
        int b = f >> 8, c = f & 255;
        float4 v = act4[(size_t)b * 65536 + (k0 >> 2) + c];
        int b2 = b >> 1, lo = b & 1;
        int cx = (c >> 2) & 3;
        int base = b2 * FC_KC + c * 4;
        smf[2 * (base + (0 ^ cx)) + lo] = v.x;
        smf[2 * (base + (1 ^ cx)) + lo] = v.y;
        smf[2 * (base + (2 ^ cx)) + lo] = v.z;
        smf[2 * (base + (3 ^ cx)) + lo] = v.w;
    }

    const int warp = tid >> 5, lane = tid & 31;
    const int ob = warp * 4;
    const int xv = (lane >> 2) & 3;

    u64t acc[4][8];
#pragma unroll
    for (int j = 0; j < 4; j++)
#pragma unroll
        for (int b2 = 0; b2 < 8; b2++) acc[j][b2] = 0ull;

    for (int sc = 0; sc < 8; sc++) {
        if (sc <= 5) cpa_wait<2>();
        else if (sc == 6) cpa_wait<1>();
        else cpa_wait<0>();
        __syncthreads();

        const float* wb = wbufs + (sc % 3) * 4096;
        float wv[4][4];
#pragma unroll
        for (int j = 0; j < 4; j++) {
            float4 w4 = *(const float4*)&wb[(ob + j) * 128 + lane * 4];
            wv[j][0] = w4.x; wv[j][1] = w4.y; wv[j][2] = w4.z; wv[j][3] = w4.w;
        }
        const int i0 = sc * 128 + lane * 4;
#pragma unroll
        for (int kk = 0; kk < 4; kk++) {
            const int ik = i0 + (kk ^ xv);
            u64t a[8];
#pragma unroll
            for (int b2 = 0; b2 < 8; b2++)
                a[b2] = *(const u64t*)&sm2[b2 * FC_KC + ik];
#pragma unroll
            for (int j = 0; j < 4; j++) {
                u64t wd = dup2(wv[j][kk]);
#pragma unroll
                for (int b2 = 0; b2 < 8; b2++)
                    fma2(acc[j][b2], wd, a[b2]);
            }
        }
        __syncthreads();
        if (sc + 3 < 8) loadW(sc + 3);
    }

#pragma unroll
    for (int j = 0; j < 4; j++)
#pragma unroll
        for (int b2 = 0; b2 < 8; b2++) {
#pragma unroll
            for (int off = 16; off >= 1; off >>= 1) {
                u64t o = __shfl_down_sync(0xffffffffu, acc[j][b2], off);
                acc[j][b2] = add2(acc[j][b2], o);
            }
        }
    if (lane == 0) {
#pragma unroll
        for (int j = 0; j < 4; j++) {
            size_t base = ((size_t)blockIdx.x * 512 + o0 + ob + j) * 16;
#pragma unroll
            for (int b2 = 0; b2 < 8; b2++) {
                float2 f = unp2(acc[j][b2]);
                g_part[base + 2 * b2]     = f.x;
                g_part[base + 2 * b2 + 1] = f.y;
            }
        }
    }
}

__global__ void __launch_bounds__(256) reduce_fc(const float* __restrict__ bf,
                                                 float* __restrict__ out)
{
    __shared__ float red[8][33];
    const int t = threadIdx.x;
    const int oi = blockIdx.x * 32 + (t & 31);
    const int part = t >> 5;
    const int o = oi >> 4, b = oi & 15;
    float s = 0.f;
#pragma unroll 8
    for (int ks = part * 32; ks < part * 32 + 32; ks++)
        s += g_part[((size_t)ks * 512 + o) * 16 + b];
    red[part][t & 31] = s;
    __syncthreads();
    if (t < 32) {
        float tot = 0.f;
#pragma unroll
        for (int j = 0; j < 8; j++) tot += red[j][t];
        int oo = blockIdx.x * 32 + t;
        out[(oo & 15) * 512 + (oo >> 4)] = tot + bf[oo >> 4];
    }
}

// ===========================================================================
extern "C" void kernel_launch(void* const* d_in, const int* in_sizes, int n_in,
                              void* d_out, int out_size)
{
    const float* q  = (const float*)d_in[0];
    const float* k  = (const float*)d_in[1];
    const float* v  = (const float*)d_in[2];
    const float* Wq = (const float*)d_in[3];
    const float* bq = (const float*)d_in[4];
    const float* Wk = (const float*)d_in[5];
    const float* bk = (const float*)d_in[6];
    const float* Wv = (const float*)d_in[7];
    const float* bv = (const float*)d_in[8];
    const float* Wf = (const float*)d_in[9];
    const float* bf = (const float*)d_in[10];
    float* out = (float*)d_out;

    cudaFuncSetAttribute(proj_mma, cudaFuncAttributeMaxDynamicSharedMemorySize, PJ_SMEM);
    cudaFuncSetAttribute(attn_kernel, cudaFuncAttributeMaxDynamicSharedMemorySize,
                         ATTN2_SMEM);
    cudaFuncSetAttribute(fc_kernel, cudaFuncAttributeMaxDynamicSharedMemorySize,
                         FC_SMEM_BYTES);

    cvt_kernel<<<13056, 256>>>(q, k, v, Wq, Wk, Wv);
    proj_mma<<<dim3(4, 64, 3), 256, PJ_SMEM>>>(bq, bk, bv);
    attn_kernel<<<dim3(8, 128), 512, ATTN2_SMEM>>>(out + 8192);
    fc_kernel<<<dim3(256, 16), 256, FC_SMEM_BYTES>>>(Wf);
    reduce_fc<<<256, 256>>>(bf, out);
}

// round 14
// speedup vs baseline: 1.1959x; 1.1118x over previous
#include <cuda_runtime.h>
#include <cuda_bf16.h>
#include <cstdint>

// ---------------------------------------------------------------------------
// MultiHeadAttention: B=16, L=512, D=512, H=8, DK=DV=64, TEMP=8
// out = ( output[16,512], attn[128,512,512] ) concatenated in d_out (fp32)
// R13: fc -> mma.sync (acc in tensor regs) with in-kernel Wf bf16-split
// ---------------------------------------------------------------------------

typedef unsigned long long u64t;

// ------------------------- scratch (static device mem) ---------------------
__device__ __align__(16) float g_act[16 * 512 * 512];     // [b][i]
__device__ __align__(16) float g_part[256 * 512 * 16];    // [ksplit][o][b]
__device__ __align__(16) __nv_bfloat16 g_xhi[3 * 8192 * 512];
__device__ __align__(16) __nv_bfloat16 g_xlo[3 * 8192 * 512];
__device__ __align__(16) __nv_bfloat16 g_whi[3 * 512 * 512];
__device__ __align__(16) __nv_bfloat16 g_wlo[3 * 512 * 512];
// head-major bf16 hi/lo projections: [h*16+b][l][64]
__device__ __align__(16) __nv_bfloat16 g_qBh[128 * 512 * 64];
__device__ __align__(16) __nv_bfloat16 g_qBl[128 * 512 * 64];
__device__ __align__(16) __nv_bfloat16 g_kBh[128 * 512 * 64];
__device__ __align__(16) __nv_bfloat16 g_kBl[128 * 512 * 64];
__device__ __align__(16) __nv_bfloat16 g_vBh[128 * 512 * 64];
__device__ __align__(16) __nv_bfloat16 g_vBl[128 * 512 * 64];
// act transposed bf16 hi/lo: [i][16 b]
__device__ __align__(16) __nv_bfloat16 g_aBh[262144 * 16];
__device__ __align__(16) __nv_bfloat16 g_aBl[262144 * 16];

// ------------------------- helpers -----------------------------------------
__device__ __forceinline__ uint32_t smem_u32(const void* p) {
    uint32_t a;
    asm("{ .reg .u64 t; cvta.to.shared.u64 t, %1; cvt.u32.u64 %0, t; }"
        : "=r"(a) : "l"(p));
    return a;
}
__device__ __forceinline__ void ldm4(uint32_t* r, uint32_t addr) {
    asm volatile("ldmatrix.sync.aligned.m8n8.x4.shared.b16 {%0,%1,%2,%3}, [%4];"
                 : "=r"(r[0]), "=r"(r[1]), "=r"(r[2]), "=r"(r[3]) : "r"(addr));
}
__device__ __forceinline__ void ldm4t(uint32_t* r, uint32_t addr) {
    asm volatile("ldmatrix.sync.aligned.m8n8.x4.trans.shared.b16 {%0,%1,%2,%3}, [%4];"
                 : "=r"(r[0]), "=r"(r[1]), "=r"(r[2]), "=r"(r[3]) : "r"(addr));
}
__device__ __forceinline__ void mma16816(float* c, const uint32_t* a,
                                         const uint32_t* b) {
    asm volatile(
        "mma.sync.aligned.m16n8k16.row.col.f32.bf16.bf16.f32 "
        "{%0,%1,%2,%3}, {%4,%5,%6,%7}, {%8,%9}, {%0,%1,%2,%3};"
        : "+f"(c[0]), "+f"(c[1]), "+f"(c[2]), "+f"(c[3])
        : "r"(a[0]), "r"(a[1]), "r"(a[2]), "r"(a[3]), "r"(b[0]), "r"(b[1]));
}
__device__ __forceinline__ void cpa16(uint32_t sa, const void* ga) {
    asm volatile("cp.async.cg.shared.global [%0], [%1], 16;"
                 :: "r"(sa), "l"(ga) : "memory");
}
__device__ __forceinline__ void cpa_commit() {
    asm volatile("cp.async.commit_group;" ::: "memory");
}
template <int N>
__device__ __forceinline__ void cpa_wait() {
    asm volatile("cp.async.wait_group %0;" :: "n"(N) : "memory");
}

// ===========================================================================
// cvt_kernel: fp32 -> (bf16 hi, bf16 lo) split for X (q,k,v) and W (Wq,Wk,Wv)
// ===========================================================================
__global__ void __launch_bounds__(256) cvt_kernel(
    const float* __restrict__ q, const float* __restrict__ k,
    const float* __restrict__ v,
    const float* __restrict__ Wq, const float* __restrict__ Wk,
    const float* __restrict__ Wv)
{
    const int t = blockIdx.x * 256 + threadIdx.x;
    const int XN4 = 3 * 1048576;
    const int WN4 = 3 * 65536;
    if (t >= XN4 + WN4) return;

    const float* src;
    __nv_bfloat16 *dh, *dl;
    size_t off4;
    if (t < XN4) {
        int z = t >> 20, i = t & 1048575;
        src = (z == 0) ? q : (z == 1) ? k : v;
        dh = g_xhi + (size_t)z * 4194304; dl = g_xlo + (size_t)z * 4194304;
        off4 = i;
    } else {
        int t2 = t - XN4;
        int z = t2 >> 16, i = t2 & 65535;
        src = (z == 0) ? Wq : (z == 1) ? Wk : Wv;
        dh = g_whi + (size_t)z * 262144; dl = g_wlo + (size_t)z * 262144;
        off4 = i;
    }
    float4 x = *(const float4*)(src + off4 * 4);
    float a[4] = { x.x, x.y, x.z, x.w };
    __nv_bfloat16 h[4], l[4];
#pragma unroll
    for (int j = 0; j < 4; j++) {
        h[j] = __float2bfloat16(a[j]);
        l[j] = __float2bfloat16(a[j] - __bfloat162float(h[j]));
    }
    __nv_bfloat162* ph = (__nv_bfloat162*)(dh + off4 * 4);
    __nv_bfloat162* pl = (__nv_bfloat162*)(dl + off4 * 4);
    ph[0] = __halves2bfloat162(h[0], h[1]); ph[1] = __halves2bfloat162(h[2], h[3]);
    pl[0] = __halves2bfloat162(l[0], l[1]); pl[1] = __halves2bfloat162(l[2], l[3]);
}

// ===========================================================================
// proj_mma v2 (R12): K-chunk 32, 2 CTAs/SM.
// ===========================================================================
#define RS2    80
#define MHALF2 10240
#define CH_BUF2 40960
#define PJ_SMEM (2 * CH_BUF2)

__global__ void __launch_bounds__(256, 2) proj_mma(
    const float* __restrict__ bq, const float* __restrict__ bk,
    const float* __restrict__ bv)
{
    extern __shared__ char smem[];
    const uint32_t sb = smem_u32(smem);
    const int tid = threadIdx.x;
    const int wid = tid >> 5, lane = tid & 31;
    const int warp_m = wid & 3, warp_n = wid >> 2;

    const int z = blockIdx.z;
    const int m0 = blockIdx.y * 128;
    const int n0 = blockIdx.x * 128;
    const float* bias = (z == 0) ? bq : (z == 1) ? bk : bv;
    __nv_bfloat16* dH = (z == 0) ? g_qBh : (z == 1) ? g_kBh : g_vBh;
    __nv_bfloat16* dL = (z == 0) ? g_qBl : (z == 1) ? g_kBl : g_vBl;

    const __nv_bfloat16* gm[4] = {
        g_xhi + ((size_t)z * 8192 + m0) * 512,
        g_xlo + ((size_t)z * 8192 + m0) * 512,
        g_whi + ((size_t)z * 512 + n0) * 512,
        g_wlo + ((size_t)z * 512 + n0) * 512 };

    const uint32_t a_row  = lane & 15;
    const uint32_t a_koff = (lane >> 4) * 16;
    const uint32_t b_nrow = ((lane >> 4) * 8) + (lane & 7);
    const uint32_t b_koff = ((lane >> 3) & 1) * 16;

    float acc[2][8][4];
#pragma unroll
    for (int mt = 0; mt < 2; mt++)
#pragma unroll
        for (int nt = 0; nt < 8; nt++)
#pragma unroll
            for (int j = 0; j < 4; j++) acc[mt][nt][j] = 0.f;

    auto load_chunk = [&](int c) {
        const int kc = c * 32;
        const uint32_t base = sb + (uint32_t)(c & 1) * CH_BUF2;
#pragma unroll
        for (int i = 0; i < 8; i++) {
            int idx = tid + i * 256;
            int mat = idx >> 9, r2 = idx & 511;
            int row = r2 >> 2, seg = r2 & 3;
            cpa16(base + mat * MHALF2 + row * RS2 + seg * 16,
                  gm[mat] + (size_t)row * 512 + kc + seg * 8);
        }
        cpa_commit();
    };

    load_chunk(0);
    load_chunk(1);

    for (int c = 0; c < 16; c++) {
        if (c < 15) cpa_wait<1>(); else cpa_wait<0>();
        __syncthreads();

        const uint32_t bufb = sb + (uint32_t)(c & 1) * CH_BUF2;
        const uint32_t aBase = bufb + (warp_m * 32 + a_row) * RS2 + a_koff;
        const uint32_t bBase = bufb + 2 * MHALF2 +
                               (warp_n * 64 + b_nrow) * RS2 + b_koff;
#pragma unroll
        for (int ks = 0; ks < 2; ks++) {
            uint32_t aH[2][4], aL[2][4], bH[8][2], bL[8][2];
#pragma unroll
            for (int mt = 0; mt < 2; mt++) {
                uint32_t ad = aBase + mt * 16 * RS2 + ks * 32;
                ldm4(aH[mt], ad);
                ldm4(aL[mt], ad + MHALF2);
            }
#pragma unroll
            for (int nb = 0; nb < 4; nb++) {
                uint32_t bd = bBase + nb * 16 * RS2 + ks * 32;
                uint32_t r[4];
                ldm4(r, bd);
                bH[2 * nb][0] = r[0]; bH[2 * nb][1] = r[1];
                bH[2 * nb + 1][0] = r[2]; bH[2 * nb + 1][1] = r[3];
                ldm4(r, bd + MHALF2);
                bL[2 * nb][0] = r[0]; bL[2 * nb][1] = r[1];
                bL[2 * nb + 1][0] = r[2]; bL[2 * nb + 1][1] = r[3];
            }
#pragma unroll
            for (int mt = 0; mt < 2; mt++)
#pragma unroll
                for (int nt = 0; nt < 8; nt++) {
                    mma16816(acc[mt][nt], aH[mt], bH[nt]);
                    mma16816(acc[mt][nt], aH[mt], bL[nt]);
                    mma16816(acc[mt][nt], aL[mt], bH[nt]);
                }
        }
        __syncthreads();
        if (c + 2 < 16) load_chunk(c + 2);
    }

    float* stage = (float*)smem;
#pragma unroll
    for (int mt = 0; mt < 2; mt++)
#pragma unroll
        for (int nt = 0; nt < 8; nt++) {
            int row = warp_m * 32 + mt * 16 + (lane >> 2);
            int col = warp_n * 64 + nt * 8 + (lane & 3) * 2;
            *(float2*)&stage[row * 132 + col] =
                make_float2(acc[mt][nt][0], acc[mt][nt][1]);
            *(float2*)&stage[(row + 8) * 132 + col] =
                make_float2(acc[mt][nt][2], acc[mt][nt][3]);
        }
    __syncthreads();

    for (int f = tid; f < 4096; f += 256) {
        int row = f >> 5, c4 = f & 31;
        int nn = c4 * 4;
        int rg = m0 + row, bbi = rg >> 9, ll = rg & 511;
        int hh2 = (n0 + nn) >> 6, d = nn & 63;
        float r[4];
#pragma unroll
        for (int j = 0; j < 4; j++)
            r[j] = stage[row * 132 + nn + j] + __ldg(&bias[n0 + nn + j]);
        __nv_bfloat16 h[4], l[4];
#pragma unroll
        for (int j = 0; j < 4; j++) {
            h[j] = __float2bfloat16(r[j]);
            l[j] = __float2bfloat16(r[j] - __bfloat162float(h[j]));
        }
        size_t off = (((size_t)hh2 * 16 + bbi) * 512 + ll) * 64 + d;
        __nv_bfloat162 hp0 = __halves2bfloat162(h[0], h[1]);
        __nv_bfloat162 hp1 = __halves2bfloat162(h[2], h[3]);
        __nv_bfloat162 lp0 = __halves2bfloat162(l[0], l[1]);
        __nv_bfloat162 lp1 = __halves2bfloat162(l[2], l[3]);
        uint2 uh, ul;
        uh.x = *(uint32_t*)&hp0; uh.y = *(uint32_t*)&hp1;
        ul.x = *(uint32_t*)&lp0; ul.y = *(uint32_t*)&lp1;
        *(uint2*)&dH[off] = uh;
        *(uint2*)&dL[off] = ul;
    }
}

// ===========================================================================
// attn v3 (R10): CTA per (hb, qtile 64), 512 threads, mma.sync both GEMMs.
// ===========================================================================
#define AQ   133120
#define AC   151552
#define AIVF 56320
#define ATTN2_SMEM 225536

__global__ void __launch_bounds__(512) attn_kernel(float* __restrict__ attn_out)
{
    extern __shared__ char smb[];
    float* smf = (float*)smb;
    const uint32_t sb = smem_u32(smb);
    const int tid = threadIdx.x;
    const int wid = tid >> 5, lane = tid & 31;
    const int hb = blockIdx.y;
    const int q0 = blockIdx.x * 64;
    const int bb = hb & 15, hh = hb >> 4;

    const __nv_bfloat16* kh = g_kBh + (size_t)hb * 512 * 64;
    const __nv_bfloat16* kl = g_kBl + (size_t)hb * 512 * 64;
    const __nv_bfloat16* vh = g_vBh + (size_t)hb * 512 * 64;
    const __nv_bfloat16* vl = g_vBl + (size_t)hb * 512 * 64;

    auto loadK = [&](int nt) {
        const uint32_t base = sb + AC + (uint32_t)(nt & 1) * 36864;
#pragma unroll
        for (int i = 0; i < 4; i++) {
            int f = tid + i * 512;
            int mat = f >> 10, idx = f & 1023;
            int rw = idx >> 3, sg = idx & 7;
            const __nv_bfloat16* g = mat ? kl : kh;
            cpa16(base + mat * 18432 + rw * 144 + sg * 16,
                  g + (size_t)(nt * 128 + rw) * 64 + sg * 8);
        }
    };
    auto loadV = [&](int nt) {
        const uint32_t base = sb + AC + 34816;
#pragma unroll
        for (int i = 0; i < 4; i++) {
            int f = tid + i * 512;
            int mat = f >> 10, idx = f & 1023;
            int rw = idx >> 3, sg = idx & 7;
            const __nv_bfloat16* g = mat ? vl : vh;
            cpa16(base + mat * 18432 + rw * 144 + sg * 16,
                  g + (size_t)(nt * 128 + rw) * 64 + sg * 8);
        }
    };

    {
        const __nv_bfloat16* qhp = g_qBh + ((size_t)hb * 512 + q0) * 64;
        const __nv_bfloat16* qlp = g_qBl + ((size_t)hb * 512 + q0) * 64;
#pragma unroll
        for (int i = 0; i < 2; i++) {
            int f = tid + i * 512;
            int mat = f >> 9, idx = f & 511;
            int rw = idx >> 3, sg = idx & 7;
            const __nv_bfloat16* g = mat ? qlp : qhp;
            cpa16(sb + AQ + mat * 9216 + rw * 144 + sg * 16,
                  g + (size_t)rw * 64 + sg * 8);
        }
        loadK(0); cpa_commit();
        loadK(1); cpa_commit();
    }

    // ---- Phase 1: S = QK^T / 8 ----
    {
        const int qb = wid & 3, nq = wid >> 2;
        const uint32_t aAddr = sb + AQ +
            (uint32_t)((qb * 16 + (lane & 15)) * 144 + ((lane >> 4) * 8) * 2);
        cpa_wait<1>(); __syncthreads();
        uint32_t aH[4][4], aL[4][4];
#pragma unroll
        for (int ks = 0; ks < 4; ks++) {
            ldm4(aH[ks], aAddr + ks * 32);
            ldm4(aL[ks], aAddr + 9216 + ks * 32);
        }
        const uint32_t bOff = (uint32_t)(
            (nq * 32 + ((lane >> 4) * 8) + (lane & 7)) * 144 +
            (((lane >> 3) & 1) * 8) * 2);

        for (int nt = 0; nt < 4; nt++) {
            if (nt == 3) { cpa_wait<0>(); __syncthreads(); }
            else if (nt > 0) { cpa_wait<1>(); __syncthreads(); }
            const uint32_t Bb = sb + AC + (uint32_t)(nt & 1) * 36864 + bOff;
            float acc[4][4];
#pragma unroll
            for (int nb = 0; nb < 4; nb++)
#pragma unroll
                for (int j = 0; j < 4; j++) acc[nb][j] = 0.f;
#pragma unroll
            for (int ks = 0; ks < 4; ks++) {
                uint32_t bH[4][2], bL[4][2];
#pragma unroll
                for (int nb4 = 0; nb4 < 2; nb4++) {
                    uint32_t r[4];
                    ldm4(r, Bb + nb4 * 16 * 144 + ks * 32);
                    bH[2 * nb4][0] = r[0]; bH[2 * nb4][1] = r[1];
                    bH[2 * nb4 + 1][0] = r[2]; bH[2 * nb4 + 1][1] = r[3];
                    ldm4(r, Bb + 18432 + nb4 * 16 * 144 + ks * 32);
                    bL[2 * nb4][0] = r[0]; bL[2 * nb4][1] = r[1];
                    bL[2 * nb4 + 1][0] = r[2]; bL[2 * nb4 + 1][1] = r[3];
                }
#pragma unroll
                for (int nb = 0; nb < 4; nb++) mma16816(acc[nb], aH[ks], bH[nb]);
#pragma unroll
                for (int nb = 0; nb < 4; nb++) mma16816(acc[nb], aH[ks], bL[nb]);
#pragma unroll
                for (int nb = 0; nb < 4; nb++) mma16816(acc[nb], aL[ks], bH[nb]);
            }
            int row = qb * 16 + (lane >> 2);
#pragma unroll
            for (int nb = 0; nb < 4; nb++) {
                int col = nt * 128 + nq * 32 + nb * 8 + (lane & 3) * 2;
                *(float2*)&smf[row * 520 + col] =
                    make_float2(acc[nb][0] * 0.125f, acc[nb][1] * 0.125f);
                *(float2*)&smf[(row + 8) * 520 + col] =
                    make_float2(acc[nb][2] * 0.125f, acc[nb][3] * 0.125f);
            }
            __syncthreads();
            if (nt < 2) { loadK(nt + 2); cpa_commit(); }
        }
    }

    loadV(0); cpa_commit();

    // ---- Phase 2: softmax + attn writeback ----
    {
        for (int qi = 0; qi < 4; qi++) {
            int ql = wid * 4 + qi;
            float* srow = &smf[ql * 520];
            float m = -3.4e38f;
#pragma unroll
            for (int s = 0; s < 4; s++) {
                float4 v = *(const float4*)&srow[(s * 32 + lane) * 4];
                m = fmaxf(m, fmaxf(fmaxf(v.x, v.y), fmaxf(v.z, v.w)));
            }
#pragma unroll
            for (int off = 16; off >= 1; off >>= 1)
                m = fmaxf(m, __shfl_xor_sync(0xffffffffu, m, off));
            float sum = 0.f;
#pragma unroll
            for (int s = 0; s < 4; s++) {
                float4* p = (float4*)&srow[(s * 32 + lane) * 4];
                float4 v = *p;
                v.x = __expf(v.x - m); v.y = __expf(v.y - m);
                v.z = __expf(v.z - m); v.w = __expf(v.w - m);
                *p = v;
                sum += v.x + v.y + v.z + v.w;
            }
#pragma unroll
            for (int off = 16; off >= 1; off >>= 1)
                sum += __shfl_xor_sync(0xffffffffu, sum, off);
            float iv = 1.0f / sum;
            if (lane == 0) smf[AIVF + ql] = iv;
            float* drow = attn_out + ((size_t)hb * 512 + q0 + ql) * 512;
#pragma unroll
            for (int s = 0; s < 4; s++) {
                float4 v = *(const float4*)&srow[(s * 32 + lane) * 4];
                v.x *= iv; v.y *= iv; v.z *= iv; v.w *= iv;
                *(float4*)&drow[(s * 32 + lane) * 4] = v;
            }
        }
    }
    __syncthreads();

    // ---- Phase 3: O = P V ----
    {
        const int qb = wid & 3, dvh = wid >> 2;
        float oacc[2][4];
#pragma unroll
        for (int db = 0; db < 2; db++)
#pragma unroll
            for (int j = 0; j < 4; j++) oacc[db][j] = 0.f;

        const uint32_t pAddr = sb + AC +
            (uint32_t)((qb * 16 + (lane & 15)) * 272 + (lane >> 4) * 16);
        const uint32_t vAddr = sb + AC + 34816 +
            (uint32_t)((lane & 15) * 144 + ((lane >> 4) * 8 + dvh * 16) * 2);

        for (int nt = 0; nt < 4; nt++) {
#pragma unroll
            for (int it = 0; it < 4; it++) {
                int idx = tid + it * 512;
                int qq = idx >> 5, c4 = idx & 31;
                float4 s = *(const float4*)&smf[qq * 520 + nt * 128 + c4 * 4];
                float iv = smf[AIVF + qq];
                float p[4] = { s.x * iv, s.y * iv, s.z * iv, s.w * iv };
                __nv_bfloat16 h[4], l[4];
#pragma unroll
                for (int j = 0; j < 4; j++) {
                    h[j] = __float2bfloat16(p[j]);
                    l[j] = __float2bfloat16(p[j] - __bfloat162float(h[j]));
                }
                __nv_bfloat162 hp0 = __halves2bfloat162(h[0], h[1]);
                __nv_bfloat162 hp1 = __halves2bfloat162(h[2], h[3]);
                __nv_bfloat162 lp0 = __halves2bfloat162(l[0], l[1]);
                __nv_bfloat162 lp1 = __halves2bfloat162(l[2], l[3]);
                uint2 uh, ul;
                uh.x = *(uint32_t*)&hp0; uh.y = *(uint32_t*)&hp1;
                ul.x = *(uint32_t*)&lp0; ul.y = *(uint32_t*)&lp1;
                *(uint2*)(smb + AC + qq * 272 + c4 * 8) = uh;
                *(uint2*)(smb + AC + 17408 + qq * 272 + c4 * 8) = ul;
            }
            cpa_wait<0>(); __syncthreads();
#pragma unroll
            for (int ks = 0; ks < 8; ks++) {
                uint32_t pH[4], pL[4];
                ldm4(pH, pAddr + ks * 32);
                ldm4(pL, pAddr + 17408 + ks * 32);
                uint32_t vH[2][2], vL[2][2], r[4];
                ldm4t(r, vAddr + ks * 16 * 144);
                vH[0][0] = r[0]; vH[0][1] = r[1]; vH[1][0] = r[2]; vH[1][1] = r[3];
                ldm4t(r, vAddr + 18432 + ks * 16 * 144);
                vL[0][0] = r[0]; vL[0][1] = r[1]; vL[1][0] = r[2]; vL[1][1] = r[3];
#pragma unroll
                for (int db = 0; db < 2; db++) mma16816(oacc[db], pH, vH[db]);
#pragma unroll
                for (int db = 0; db < 2; db++) mma16816(oacc[db], pH, vL[db]);
#pragma unroll
                for (int db = 0; db < 2; db++) mma16816(oacc[db], pL, vH[db]);
            }
            __syncthreads();
            if (nt < 3) { loadV(nt + 1); cpa_commit(); }
        }

        int row = qb * 16 + (lane >> 2);
#pragma unroll
        for (int db = 0; db < 2; db++) {
            int dv = dvh * 16 + db * 8 + (lane & 3) * 2;
            *(float2*)&g_act[(((size_t)bb * 512 + q0 + row) * 8 + hh) * 64 + dv] =
                make_float2(oacc[db][0], oacc[db][1]);
            *(float2*)&g_act[(((size_t)bb * 512 + q0 + row + 8) * 8 + hh) * 64 + dv] =
                make_float2(oacc[db][2], oacc[db][3]);
        }
    }
}

// ===========================================================================
// actcvt: g_act [b][i] fp32 -> g_aBh/g_aBl [i][16 b] bf16 (transposed tiles)
// ===========================================================================
__global__ void __launch_bounds__(256) actcvt()
{
    __shared__ float sm[16][65];
    const int tid = threadIdx.x;
    const int i0 = blockIdx.x * 64;

    for (int f = tid; f < 1024; f += 256) {
        int b = f >> 6, ii = f & 63;
        sm[b][ii] = g_act[(size_t)b * 262144 + i0 + ii];
    }
    __syncthreads();

    for (int f = tid; f < 512; f += 256) {
        int ii = f >> 3, bp = f & 7;
        float x0 = sm[bp * 2][ii], x1 = sm[bp * 2 + 1][ii];
        __nv_bfloat16 h0 = __float2bfloat16(x0);
        __nv_bfloat16 h1 = __float2bfloat16(x1);
        __nv_bfloat16 l0 = __float2bfloat16(x0 - __bfloat162float(h0));
        __nv_bfloat16 l1 = __float2bfloat16(x1 - __bfloat162float(h1));
        __nv_bfloat162 hp = __halves2bfloat162(h0, h1);
        __nv_bfloat162 lp = __halves2bfloat162(l0, l1);
        *(uint32_t*)&g_aBh[(size_t)(i0 + ii) * 16 + bp * 2] = *(uint32_t*)&hp;
        *(uint32_t*)&g_aBl[(size_t)(i0 + ii) * 16 + bp * 2] = *(uint32_t*)&lp;
    }
}

// ===========================================================================
// fc_mma: out[b][o] = sum_i act[b][i]*Wf[o][i] via mma.sync bf16 split-2.
// 256 thr (8 warps), grid (256 ksplit, 16 oblocks of 32). Sub-chunk = 128 k.
// Ring depth 3: slot = Wf fp32 [32][128] (16KB) + actH/L [128 k][16 b] pad48
// (6KB each). Per sc: convert Wf -> wcvt bf16 [32 o][128 k] stride 272;
// warp w owns k16 step w: A = ldm4t(act), B = ldm4(wcvt), 12 mma.
// End: cross-warp k-partial reduce via smem -> g_part (layout unchanged).
// ===========================================================================
#define FCM_SLOT   28672                    // 16384 + 6144 + 6144
#define FCM_ACTH   16384
#define FCM_ACTL   22528
#define FCM_WCVT_H 86016                    // 3 * FCM_SLOT
#define FCM_WCVT_L 94720                    // +8704 (32 rows x 272B)
#define FCM_SMEM   103424

__global__ void __launch_bounds__(256, 2) fc_kernel(const float* __restrict__ Wf)
{
    extern __shared__ char smc[];
    const uint32_t sb = smem_u32(smc);
    const int tid = threadIdx.x;
    const int wid = tid >> 5, lane = tid & 31;
    const int k0 = blockIdx.x * 1024;
    const int o0 = blockIdx.y * 32;

    auto loadSlot = [&](int sc) {
        const uint32_t base = sb + (uint32_t)(sc % 3) * FCM_SLOT;
        const float* wsrc = Wf + (size_t)o0 * 262144 + k0 + sc * 128;
#pragma unroll
        for (int i = 0; i < 4; i++) {
            int c = tid + i * 256;                 // 0..1023
            int row = c >> 5, sg = c & 31;         // 32 x 16B per o-row
            cpa16(base + row * 512 + sg * 16,
                  wsrc + (size_t)row * 262144 + sg * 4);
        }
        {
            int row = tid >> 1, half = tid & 1;    // act rows 0..127
            size_t gi = (size_t)(k0 + sc * 128 + row) * 16 + half * 8;
            cpa16(base + FCM_ACTH + row * 48 + half * 16, g_aBh + gi);
            cpa16(base + FCM_ACTL + row * 48 + half * 16, g_aBl + gi);
        }
        cpa_commit();
    };
    loadSlot(0); loadSlot(1); loadSlot(2);

    float acc[4][4];
#pragma unroll
    for (int nb = 0; nb < 4; nb++)
#pragma unroll
        for (int j = 0; j < 4; j++) acc[nb][j] = 0.f;

    // per-warp ldmatrix lane addressing
    const uint32_t a_off = (uint32_t)(
        (wid * 16 + (lane & 7) + ((lane >> 4) & 1) * 8) * 48 +
        ((lane >> 3) & 1) * 16);
    const uint32_t b_off = (uint32_t)(
        (((lane >> 4) * 8) + (lane & 7)) * 272 + ((lane >> 3) & 1) * 16 +
        wid * 32);

    for (int sc = 0; sc < 8; sc++) {
        if (sc <= 5) cpa_wait<2>();
        else if (sc == 6) cpa_wait<1>();
        else cpa_wait<0>();
        __syncthreads();

        const uint32_t base = sb + (uint32_t)(sc % 3) * FCM_SLOT;
        // convert Wf fp32 slot -> wcvt bf16 hi/lo [32 o][128 k] stride 272B
        const float2* wsl = (const float2*)(smc + (sc % 3) * FCM_SLOT);
#pragma unroll
        for (int j = 0; j < 8; j++) {
            int e2 = tid + j * 256;                // float2 index 0..2047
            float2 w2 = wsl[e2];
            int o = e2 >> 6, kb = (e2 & 63) * 4;   // byte offset of k pair
            __nv_bfloat16 h0 = __float2bfloat16(w2.x);
            __nv_bfloat16 h1 = __float2bfloat16(w2.y);
            __nv_bfloat16 l0 = __float2bfloat16(w2.x - __bfloat162float(h0));
            __nv_bfloat16 l1 = __float2bfloat16(w2.y - __bfloat162float(h1));
            __nv_bfloat162 hp = __halves2bfloat162(h0, h1);
            __nv_bfloat162 lp = __halves2bfloat162(l0, l1);
            *(uint32_t*)(smc + FCM_WCVT_H + o * 272 + kb) = *(uint32_t*)&hp;
            *(uint32_t*)(smc + FCM_WCVT_L + o * 272 + kb) = *(uint32_t*)&lp;
        }
        __syncthreads();

        uint32_t aH[4], aL[4];
        ldm4t(aH, base + FCM_ACTH + a_off);
        ldm4t(aL, base + FCM_ACTL + a_off);
        uint32_t bH[4][2], bL[4][2];
#pragma unroll
        for (int oh = 0; oh < 2; oh++) {
            uint32_t r[4];
            ldm4(r, sb + FCM_WCVT_H + oh * 16 * 272 + b_off);
            bH[2 * oh][0] = r[0]; bH[2 * oh][1] = r[1];
            bH[2 * oh + 1][0] = r[2]; bH[2 * oh + 1][1] = r[3];
            ldm4(r, sb + FCM_WCVT_L + oh * 16 * 272 + b_off);
            bL[2 * oh][0] = r[0]; bL[2 * oh][1] = r[1];
            bL[2 * oh + 1][0] = r[2]; bL[2 * oh + 1][1] = r[3];
        }
#pragma unroll
        for (int nb = 0; nb < 4; nb++) mma16816(acc[nb], aH, bH[nb]);
#pragma unroll
        for (int nb = 0; nb < 4; nb++) mma16816(acc[nb], aH, bL[nb]);
#pragma unroll
        for (int nb = 0; nb < 4; nb++) mma16816(acc[nb], aL, bH[nb]);

        __syncthreads();
        if (sc + 3 < 8) loadSlot(sc + 3);
    }

    // cross-warp reduce: redbuf [8 w][16 b][32 o] floats (reuse wcvt area)
    float* red = (float*)(smc + FCM_WCVT_H);   // 16KB < 17408 available
    __syncthreads();
    {
        int r0 = lane >> 2, c0 = (lane & 3) * 2;
#pragma unroll
        for (int nb = 0; nb < 4; nb++) {
            red[wid * 512 + r0 * 32 + nb * 8 + c0]            = acc[nb][0];
            red[wid * 512 + r0 * 32 + nb * 8 + c0 + 1]        = acc[nb][1];
            red[wid * 512 + (r0 + 8) * 32 + nb * 8 + c0]      = acc[nb][2];
            red[wid * 512 + (r0 + 8) * 32 + nb * 8 + c0 + 1]  = acc[nb][3];
        }
    }
    __syncthreads();
#pragma unroll
    for (int rep = 0; rep < 2; rep++) {
        int e = tid + rep * 256;                  // e = b*32 + o
        float s = 0.f;
#pragma unroll
        for (int w = 0; w < 8; w++) s += red[w * 512 + e];
        int b = e >> 5, o = e & 31;
        g_part[((size_t)blockIdx.x * 512 + o0 + o) * 16 + b] = s;
    }
}

__global__ void __launch_bounds__(256) reduce_fc(const float* __restrict__ bf,
                                                 float* __restrict__ out)
{
    __shared__ float red[8][33];
    const int t = threadIdx.x;
    const int oi = blockIdx.x * 32 + (t & 31);
    const int part = t >> 5;
    const int o = oi >> 4, b = oi & 15;
    float s = 0.f;
#pragma unroll 8
    for (int ks = part * 32; ks < part * 32 + 32; ks++)
        s += g_part[((size_t)ks * 512 + o) * 16 + b];
    red[part][t & 31] = s;
    __syncthreads();
    if (t < 32) {
        float tot = 0.f;
#pragma unroll
        for (int j = 0; j < 8; j++) tot += red[j][t];
        int oo = blockIdx.x * 32 + t;
        out[(oo & 15) * 512 + (oo >> 4)] = tot + bf[oo >> 4];
    }
}

// ===========================================================================
extern "C" void kernel_launch(void* const* d_in, const int* in_sizes, int n_in,
                              void* d_out, int out_size)
{
    const float* q  = (const float*)d_in[0];
    const float* k  = (const float*)d_in[1];
    const float* v  = (const float*)d_in[2];
    const float* Wq = (const float*)d_in[3];
    const float* bq = (const float*)d_in[4];
    const float* Wk = (const float*)d_in[5];
    const float* bk = (const float*)d_in[6];
    const float* Wv = (const float*)d_in[7];
    const float* bv = (const float*)d_in[8];
    const float* Wf = (const float*)d_in[9];
    const float* bf = (const float*)d_in[10];
    float* out = (float*)d_out;

    cudaFuncSetAttribute(proj_mma, cudaFuncAttributeMaxDynamicSharedMemorySize, PJ_SMEM);
    cudaFuncSetAttribute(attn_kernel, cudaFuncAttributeMaxDynamicSharedMemorySize,
                         ATTN2_SMEM);
    cudaFuncSetAttribute(fc_kernel, cudaFuncAttributeMaxDynamicSharedMemorySize,
                         FCM_SMEM);

    cvt_kernel<<<13056, 256>>>(q, k, v, Wq, Wk, Wv);
    proj_mma<<<dim3(4, 64, 3), 256, PJ_SMEM>>>(bq, bk, bv);
    attn_kernel<<<dim3(8, 128), 512, ATTN2_SMEM>>>(out + 8192);
    actcvt<<<4096, 256>>>();
    fc_kernel<<<dim3(256, 16), 256, FCM_SMEM>>>(Wf);
    reduce_fc<<<256, 256>>>(bf, out);
}

// round 15
// speedup vs baseline: 1.2667x; 1.0592x over previous
#include <cuda_runtime.h>
#include <cuda_bf16.h>
#include <cstdint>

// ---------------------------------------------------------------------------
// MultiHeadAttention: B=16, L=512, D=512, H=8, DK=DV=64, TEMP=8
// out = ( output[16,512], attn[128,512,512] ) concatenated in d_out (fp32)
// R14: fc -> tf32 mma (single pass, cvt.rna), actcvt emits tf32-rounded fp32
// ---------------------------------------------------------------------------

typedef unsigned long long u64t;

// ------------------------- scratch (static device mem) ---------------------
__device__ __align__(16) float g_act[16 * 512 * 512];     // [b][i]
__device__ __align__(16) float g_part[256 * 512 * 16];    // [ksplit][o][b]
__device__ __align__(16) __nv_bfloat16 g_xhi[3 * 8192 * 512];
__device__ __align__(16) __nv_bfloat16 g_xlo[3 * 8192 * 512];
__device__ __align__(16) __nv_bfloat16 g_whi[3 * 512 * 512];
__device__ __align__(16) __nv_bfloat16 g_wlo[3 * 512 * 512];
// head-major bf16 hi/lo projections: [h*16+b][l][64]
__device__ __align__(16) __nv_bfloat16 g_qBh[128 * 512 * 64];
__device__ __align__(16) __nv_bfloat16 g_qBl[128 * 512 * 64];
__device__ __align__(16) __nv_bfloat16 g_kBh[128 * 512 * 64];
__device__ __align__(16) __nv_bfloat16 g_kBl[128 * 512 * 64];
__device__ __align__(16) __nv_bfloat16 g_vBh[128 * 512 * 64];
__device__ __align__(16) __nv_bfloat16 g_vBl[128 * 512 * 64];
// act transposed, tf32-rounded fp32: [i][16 b]
__device__ __align__(16) float g_aT[262144 * 16];

// ------------------------- helpers -----------------------------------------
__device__ __forceinline__ uint32_t smem_u32(const void* p) {
    uint32_t a;
    asm("{ .reg .u64 t; cvta.to.shared.u64 t, %1; cvt.u32.u64 %0, t; }"
        : "=r"(a) : "l"(p));
    return a;
}
__device__ __forceinline__ void ldm4(uint32_t* r, uint32_t addr) {
    asm volatile("ldmatrix.sync.aligned.m8n8.x4.shared.b16 {%0,%1,%2,%3}, [%4];"
                 : "=r"(r[0]), "=r"(r[1]), "=r"(r[2]), "=r"(r[3]) : "r"(addr));
}
__device__ __forceinline__ void ldm4t(uint32_t* r, uint32_t addr) {
    asm volatile("ldmatrix.sync.aligned.m8n8.x4.trans.shared.b16 {%0,%1,%2,%3}, [%4];"
                 : "=r"(r[0]), "=r"(r[1]), "=r"(r[2]), "=r"(r[3]) : "r"(addr));
}
__device__ __forceinline__ void mma16816(float* c, const uint32_t* a,
                                         const uint32_t* b) {
    asm volatile(
        "mma.sync.aligned.m16n8k16.row.col.f32.bf16.bf16.f32 "
        "{%0,%1,%2,%3}, {%4,%5,%6,%7}, {%8,%9}, {%0,%1,%2,%3};"
        : "+f"(c[0]), "+f"(c[1]), "+f"(c[2]), "+f"(c[3])
        : "r"(a[0]), "r"(a[1]), "r"(a[2]), "r"(a[3]), "r"(b[0]), "r"(b[1]));
}
__device__ __forceinline__ void mma_tf32(float* c, uint32_t a0, uint32_t a1,
                                         uint32_t a2, uint32_t a3,
                                         uint32_t b0, uint32_t b1) {
    asm volatile(
        "mma.sync.aligned.m16n8k8.row.col.f32.tf32.tf32.f32 "
        "{%0,%1,%2,%3}, {%4,%5,%6,%7}, {%8,%9}, {%0,%1,%2,%3};"
        : "+f"(c[0]), "+f"(c[1]), "+f"(c[2]), "+f"(c[3])
        : "r"(a0), "r"(a1), "r"(a2), "r"(a3), "r"(b0), "r"(b1));
}
__device__ __forceinline__ uint32_t cvt_tf32(float x) {
    uint32_t u;
    asm("cvt.rna.tf32.f32 %0, %1;" : "=r"(u) : "f"(x));
    return u;
}
__device__ __forceinline__ void cpa16(uint32_t sa, const void* ga) {
    asm volatile("cp.async.cg.shared.global [%0], [%1], 16;"
                 :: "r"(sa), "l"(ga) : "memory");
}
__device__ __forceinline__ void cpa_commit() {
    asm volatile("cp.async.commit_group;" ::: "memory");
}
template <int N>
__device__ __forceinline__ void cpa_wait() {
    asm volatile("cp.async.wait_group %0;" :: "n"(N) : "memory");
}

// ===========================================================================
// cvt_kernel: fp32 -> (bf16 hi, bf16 lo) split for X (q,k,v) and W (Wq,Wk,Wv)
// ===========================================================================
__global__ void __launch_bounds__(256) cvt_kernel(
    const float* __restrict__ q, const float* __restrict__ k,
    const float* __restrict__ v,
    const float* __restrict__ Wq, const float* __restrict__ Wk,
    const float* __restrict__ Wv)
{
    const int t = blockIdx.x * 256 + threadIdx.x;
    const int XN4 = 3 * 1048576;
    const int WN4 = 3 * 65536;
    if (t >= XN4 + WN4) return;

    const float* src;
    __nv_bfloat16 *dh, *dl;
    size_t off4;
    if (t < XN4) {
        int z = t >> 20, i = t & 1048575;
        src = (z == 0) ? q : (z == 1) ? k : v;
        dh = g_xhi + (size_t)z * 4194304; dl = g_xlo + (size_t)z * 4194304;
        off4 = i;
    } else {
        int t2 = t - XN4;
        int z = t2 >> 16, i = t2 & 65535;
        src = (z == 0) ? Wq : (z == 1) ? Wk : Wv;
        dh = g_whi + (size_t)z * 262144; dl = g_wlo + (size_t)z * 262144;
        off4 = i;
    }
    float4 x = *(const float4*)(src + off4 * 4);
    float a[4] = { x.x, x.y, x.z, x.w };
    __nv_bfloat16 h[4], l[4];
#pragma unroll
    for (int j = 0; j < 4; j++) {
        h[j] = __float2bfloat16(a[j]);
        l[j] = __float2bfloat16(a[j] - __bfloat162float(h[j]));
    }
    __nv_bfloat162* ph = (__nv_bfloat162*)(dh + off4 * 4);
    __nv_bfloat162* pl = (__nv_bfloat162*)(dl + off4 * 4);
    ph[0] = __halves2bfloat162(h[0], h[1]); ph[1] = __halves2bfloat162(h[2], h[3]);
    pl[0] = __halves2bfloat162(l[0], l[1]); pl[1] = __halves2bfloat162(l[2], l[3]);
}

// ===========================================================================
// proj_mma v2 (R12): K-chunk 32, 2 CTAs/SM.
// ===========================================================================
#define RS2    80
#define MHALF2 10240
#define CH_BUF2 40960
#define PJ_SMEM (2 * CH_BUF2)

__global__ void __launch_bounds__(256, 2) proj_mma(
    const float* __restrict__ bq, const float* __restrict__ bk,
    const float* __restrict__ bv)
{
    extern __shared__ char smem[];
    const uint32_t sb = smem_u32(smem);
    const int tid = threadIdx.x;
    const int wid = tid >> 5, lane = tid & 31;
    const int warp_m = wid & 3, warp_n = wid >> 2;

    const int z = blockIdx.z;
    const int m0 = blockIdx.y * 128;
    const int n0 = blockIdx.x * 128;
    const float* bias = (z == 0) ? bq : (z == 1) ? bk : bv;
    __nv_bfloat16* dH = (z == 0) ? g_qBh : (z == 1) ? g_kBh : g_vBh;
    __nv_bfloat16* dL = (z == 0) ? g_qBl : (z == 1) ? g_kBl : g_vBl;

    const __nv_bfloat16* gm[4] = {
        g_xhi + ((size_t)z * 8192 + m0) * 512,
        g_xlo + ((size_t)z * 8192 + m0) * 512,
        g_whi + ((size_t)z * 512 + n0) * 512,
        g_wlo + ((size_t)z * 512 + n0) * 512 };

    const uint32_t a_row  = lane & 15;
    const uint32_t a_koff = (lane >> 4) * 16;
    const uint32_t b_nrow = ((lane >> 4) * 8) + (lane & 7);
    const uint32_t b_koff = ((lane >> 3) & 1) * 16;

    float acc[2][8][4];
#pragma unroll
    for (int mt = 0; mt < 2; mt++)
#pragma unroll
        for (int nt = 0; nt < 8; nt++)
#pragma unroll
            for (int j = 0; j < 4; j++) acc[mt][nt][j] = 0.f;

    auto load_chunk = [&](int c) {
        const int kc = c * 32;
        const uint32_t base = sb + (uint32_t)(c & 1) * CH_BUF2;
#pragma unroll
        for (int i = 0; i < 8; i++) {
            int idx = tid + i * 256;
            int mat = idx >> 9, r2 = idx & 511;
            int row = r2 >> 2, seg = r2 & 3;
            cpa16(base + mat * MHALF2 + row * RS2 + seg * 16,
                  gm[mat] + (size_t)row * 512 + kc + seg * 8);
        }
        cpa_commit();
    };

    load_chunk(0);
    load_chunk(1);

    for (int c = 0; c < 16; c++) {
        if (c < 15) cpa_wait<1>(); else cpa_wait<0>();
        __syncthreads();

        const uint32_t bufb = sb + (uint32_t)(c & 1) * CH_BUF2;
        const uint32_t aBase = bufb + (warp_m * 32 + a_row) * RS2 + a_koff;
        const uint32_t bBase = bufb + 2 * MHALF2 +
                               (warp_n * 64 + b_nrow) * RS2 + b_koff;
#pragma unroll
        for (int ks = 0; ks < 2; ks++) {
            uint32_t aH[2][4], aL[2][4], bH[8][2], bL[8][2];
#pragma unroll
            for (int mt = 0; mt < 2; mt++) {
                uint32_t ad = aBase + mt * 16 * RS2 + ks * 32;
                ldm4(aH[mt], ad);
                ldm4(aL[mt], ad + MHALF2);
            }
#pragma unroll
            for (int nb = 0; nb < 4; nb++) {
                uint32_t bd = bBase + nb * 16 * RS2 + ks * 32;
                uint32_t r[4];
                ldm4(r, bd);
                bH[2 * nb][0] = r[0]; bH[2 * nb][1] = r[1];
                bH[2 * nb + 1][0] = r[2]; bH[2 * nb + 1][1] = r[3];
                ldm4(r, bd + MHALF2);
                bL[2 * nb][0] = r[0]; bL[2 * nb][1] = r[1];
                bL[2 * nb + 1][0] = r[2]; bL[2 * nb + 1][1] = r[3];
            }
#pragma unroll
            for (int mt = 0; mt < 2; mt++)
#pragma unroll
                for (int nt = 0; nt < 8; nt++) {
                    mma16816(acc[mt][nt], aH[mt], bH[nt]);
                    mma16816(acc[mt][nt], aH[mt], bL[nt]);
                    mma16816(acc[mt][nt], aL[mt], bH[nt]);
                }
        }
        __syncthreads();
        if (c + 2 < 16) load_chunk(c + 2);
    }

    float* stage = (float*)smem;
#pragma unroll
    for (int mt = 0; mt < 2; mt++)
#pragma unroll
        for (int nt = 0; nt < 8; nt++) {
            int row = warp_m * 32 + mt * 16 + (lane >> 2);
            int col = warp_n * 64 + nt * 8 + (lane & 3) * 2;
            *(float2*)&stage[row * 132 + col] =
                make_float2(acc[mt][nt][0], acc[mt][nt][1]);
            *(float2*)&stage[(row + 8) * 132 + col] =
                make_float2(acc[mt][nt][2], acc[mt][nt][3]);
        }
    __syncthreads();

    for (int f = tid; f < 4096; f += 256) {
        int row = f >> 5, c4 = f & 31;
        int nn = c4 * 4;
        int rg = m0 + row, bbi = rg >> 9, ll = rg & 511;
        int hh2 = (n0 + nn) >> 6, d = nn & 63;
        float r[4];
#pragma unroll
        for (int j = 0; j < 4; j++)
            r[j] = stage[row * 132 + nn + j] + __ldg(&bias[n0 + nn + j]);
        __nv_bfloat16 h[4], l[4];
#pragma unroll
        for (int j = 0; j < 4; j++) {
            h[j] = __float2bfloat16(r[j]);
            l[j] = __float2bfloat16(r[j] - __bfloat162float(h[j]));
        }
        size_t off = (((size_t)hh2 * 16 + bbi) * 512 + ll) * 64 + d;
        __nv_bfloat162 hp0 = __halves2bfloat162(h[0], h[1]);
        __nv_bfloat162 hp1 = __halves2bfloat162(h[2], h[3]);
        __nv_bfloat162 lp0 = __halves2bfloat162(l[0], l[1]);
        __nv_bfloat162 lp1 = __halves2bfloat162(l[2], l[3]);
        uint2 uh, ul;
        uh.x = *(uint32_t*)&hp0; uh.y = *(uint32_t*)&hp1;
        ul.x = *(uint32_t*)&lp0; ul.y = *(uint32_t*)&lp1;
        *(uint2*)&dH[off] = uh;
        *(uint2*)&dL[off] = ul;
    }
}

// ===========================================================================
// attn v3 (R10): CTA per (hb, qtile 64), 512 threads, mma.sync both GEMMs.
// ===========================================================================
#define AQ   133120
#define AC   151552
#define AIVF 56320
#define ATTN2_SMEM 225536

__global__ void __launch_bounds__(512) attn_kernel(float* __restrict__ attn_out)
{
    extern __shared__ char smb[];
    float* smf = (float*)smb;
    const uint32_t sb = smem_u32(smb);
    const int tid = threadIdx.x;
    const int wid = tid >> 5, lane = tid & 31;
    const int hb = blockIdx.y;
    const int q0 = blockIdx.x * 64;
    const int bb = hb & 15, hh = hb >> 4;

    const __nv_bfloat16* kh = g_kBh + (size_t)hb * 512 * 64;
    const __nv_bfloat16* kl = g_kBl + (size_t)hb * 512 * 64;
    const __nv_bfloat16* vh = g_vBh + (size_t)hb * 512 * 64;
    const __nv_bfloat16* vl = g_vBl + (size_t)hb * 512 * 64;

    auto loadK = [&](int nt) {
        const uint32_t base = sb + AC + (uint32_t)(nt & 1) * 36864;
#pragma unroll
        for (int i = 0; i < 4; i++) {
            int f = tid + i * 512;
            int mat = f >> 10, idx = f & 1023;
            int rw = idx >> 3, sg = idx & 7;
            const __nv_bfloat16* g = mat ? kl : kh;
            cpa16(base + mat * 18432 + rw * 144 + sg * 16,
                  g + (size_t)(nt * 128 + rw) * 64 + sg * 8);
        }
    };
    auto loadV = [&](int nt) {
        const uint32_t base = sb + AC + 34816;
#pragma unroll
        for (int i = 0; i < 4; i++) {
            int f = tid + i * 512;
            int mat = f >> 10, idx = f & 1023;
            int rw = idx >> 3, sg = idx & 7;
            const __nv_bfloat16* g = mat ? vl : vh;
            cpa16(base + mat * 18432 + rw * 144 + sg * 16,
                  g + (size_t)(nt * 128 + rw) * 64 + sg * 8);
        }
    };

    {
        const __nv_bfloat16* qhp = g_qBh + ((size_t)hb * 512 + q0) * 64;
        const __nv_bfloat16* qlp = g_qBl + ((size_t)hb * 512 + q0) * 64;
#pragma unroll
        for (int i = 0; i < 2; i++) {
            int f = tid + i * 512;
            int mat = f >> 9, idx = f & 511;
            int rw = idx >> 3, sg = idx & 7;
            const __nv_bfloat16* g = mat ? qlp : qhp;
            cpa16(sb + AQ + mat * 9216 + rw * 144 + sg * 16,
                  g + (size_t)rw * 64 + sg * 8);
        }
        loadK(0); cpa_commit();
        loadK(1); cpa_commit();
    }

    // ---- Phase 1: S = QK^T / 8 ----
    {
        const int qb = wid & 3, nq = wid >> 2;
        const uint32_t aAddr = sb + AQ +
            (uint32_t)((qb * 16 + (lane & 15)) * 144 + ((lane >> 4) * 8) * 2);
        cpa_wait<1>(); __syncthreads();
        uint32_t aH[4][4], aL[4][4];
#pragma unroll
        for (int ks = 0; ks < 4; ks++) {
            ldm4(aH[ks], aAddr + ks * 32);
            ldm4(aL[ks], aAddr + 9216 + ks * 32);
        }
        const uint32_t bOff = (uint32_t)(
            (nq * 32 + ((lane >> 4) * 8) + (lane & 7)) * 144 +
            (((lane >> 3) & 1) * 8) * 2);

        for (int nt = 0; nt < 4; nt++) {
            if (nt == 3) { cpa_wait<0>(); __syncthreads(); }
            else if (nt > 0) { cpa_wait<1>(); __syncthreads(); }
            const uint32_t Bb = sb + AC + (uint32_t)(nt & 1) * 36864 + bOff;
            float acc[4][4];
#pragma unroll
            for (int nb = 0; nb < 4; nb++)
#pragma unroll
                for (int j = 0; j < 4; j++) acc[nb][j] = 0.f;
#pragma unroll
            for (int ks = 0; ks < 4; ks++) {
                uint32_t bH[4][2], bL[4][2];
#pragma unroll
                for (int nb4 = 0; nb4 < 2; nb4++) {
                    uint32_t r[4];
                    ldm4(r, Bb + nb4 * 16 * 144 + ks * 32);
                    bH[2 * nb4][0] = r[0]; bH[2 * nb4][1] = r[1];
                    bH[2 * nb4 + 1][0] = r[2]; bH[2 * nb4 + 1][1] = r[3];
                    ldm4(r, Bb + 18432 + nb4 * 16 * 144 + ks * 32);
                    bL[2 * nb4][0] = r[0]; bL[2 * nb4][1] = r[1];
                    bL[2 * nb4 + 1][0] = r[2]; bL[2 * nb4 + 1][1] = r[3];
                }
#pragma unroll
                for (int nb = 0; nb < 4; nb++) mma16816(acc[nb], aH[ks], bH[nb]);
#pragma unroll
                for (int nb = 0; nb < 4; nb++) mma16816(acc[nb], aH[ks], bL[nb]);
#pragma unroll
                for (int nb = 0; nb < 4; nb++) mma16816(acc[nb], aL[ks], bH[nb]);
            }
            int row = qb * 16 + (lane >> 2);
#pragma unroll
            for (int nb = 0; nb < 4; nb++) {
                int col = nt * 128 + nq * 32 + nb * 8 + (lane & 3) * 2;
                *(float2*)&smf[row * 520 + col] =
                    make_float2(acc[nb][0] * 0.125f, acc[nb][1] * 0.125f);
                *(float2*)&smf[(row + 8) * 520 + col] =
                    make_float2(acc[nb][2] * 0.125f, acc[nb][3] * 0.125f);
            }
            __syncthreads();
            if (nt < 2) { loadK(nt + 2); cpa_commit(); }
        }
    }

    loadV(0); cpa_commit();

    // ---- Phase 2: softmax + attn writeback ----
    {
        for (int qi = 0; qi < 4; qi++) {
            int ql = wid * 4 + qi;
            float* srow = &smf[ql * 520];
            float m = -3.4e38f;
#pragma unroll
            for (int s = 0; s < 4; s++) {
                float4 v = *(const float4*)&srow[(s * 32 + lane) * 4];
                m = fmaxf(m, fmaxf(fmaxf(v.x, v.y), fmaxf(v.z, v.w)));
            }
#pragma unroll
            for (int off = 16; off >= 1; off >>= 1)
                m = fmaxf(m, __shfl_xor_sync(0xffffffffu, m, off));
            float sum = 0.f;
#pragma unroll
            for (int s = 0; s < 4; s++) {
                float4* p = (float4*)&srow[(s * 32 + lane) * 4];
                float4 v = *p;
                v.x = __expf(v.x - m); v.y = __expf(v.y - m);
                v.z = __expf(v.z - m); v.w = __expf(v.w - m);
                *p = v;
                sum += v.x + v.y + v.z + v.w;
            }
#pragma unroll
            for (int off = 16; off >= 1; off >>= 1)
                sum += __shfl_xor_sync(0xffffffffu, sum, off);
            float iv = 1.0f / sum;
            if (lane == 0) smf[AIVF + ql] = iv;
            float* drow = attn_out + ((size_t)hb * 512 + q0 + ql) * 512;
#pragma unroll
            for (int s = 0; s < 4; s++) {
                float4 v = *(const float4*)&srow[(s * 32 + lane) * 4];
                v.x *= iv; v.y *= iv; v.z *= iv; v.w *= iv;
                *(float4*)&drow[(s * 32 + lane) * 4] = v;
            }
        }
    }
    __syncthreads();

    // ---- Phase 3: O = P V ----
    {
        const int qb = wid & 3, dvh = wid >> 2;
        float oacc[2][4];
#pragma unroll
        for (int db = 0; db < 2; db++)
#pragma unroll
            for (int j = 0; j < 4; j++) oacc[db][j] = 0.f;

        const uint32_t pAddr = sb + AC +
            (uint32_t)((qb * 16 + (lane & 15)) * 272 + (lane >> 4) * 16);
        const uint32_t vAddr = sb + AC + 34816 +
            (uint32_t)((lane & 15) * 144 + ((lane >> 4) * 8 + dvh * 16) * 2);

        for (int nt = 0; nt < 4; nt++) {
#pragma unroll
            for (int it = 0; it < 4; it++) {
                int idx = tid + it * 512;
                int qq = idx >> 5, c4 = idx & 31;
                float4 s = *(const float4*)&smf[qq * 520 + nt * 128 + c4 * 4];
                float iv = smf[AIVF + qq];
                float p[4] = { s.x * iv, s.y * iv, s.z * iv, s.w * iv };
                __nv_bfloat16 h[4], l[4];
#pragma unroll
                for (int j = 0; j < 4; j++) {
                    h[j] = __float2bfloat16(p[j]);
                    l[j] = __float2bfloat16(p[j] - __bfloat162float(h[j]));
                }
                __nv_bfloat162 hp0 = __halves2bfloat162(h[0], h[1]);
                __nv_bfloat162 hp1 = __halves2bfloat162(h[2], h[3]);
                __nv_bfloat162 lp0 = __halves2bfloat162(l[0], l[1]);
                __nv_bfloat162 lp1 = __halves2bfloat162(l[2], l[3]);
                uint2 uh, ul;
                uh.x = *(uint32_t*)&hp0; uh.y = *(uint32_t*)&hp1;
                ul.x = *(uint32_t*)&lp0; ul.y = *(uint32_t*)&lp1;
                *(uint2*)(smb + AC + qq * 272 + c4 * 8) = uh;
                *(uint2*)(smb + AC + 17408 + qq * 272 + c4 * 8) = ul;
            }
            cpa_wait<0>(); __syncthreads();
#pragma unroll
            for (int ks = 0; ks < 8; ks++) {
                uint32_t pH[4], pL[4];
                ldm4(pH, pAddr + ks * 32);
                ldm4(pL, pAddr + 17408 + ks * 32);
                uint32_t vH[2][2], vL[2][2], r[4];
                ldm4t(r, vAddr + ks * 16 * 144);
                vH[0][0] = r[0]; vH[0][1] = r[1]; vH[1][0] = r[2]; vH[1][1] = r[3];
                ldm4t(r, vAddr + 18432 + ks * 16 * 144);
                vL[0][0] = r[0]; vL[0][1] = r[1]; vL[1][0] = r[2]; vL[1][1] = r[3];
#pragma unroll
                for (int db = 0; db < 2; db++) mma16816(oacc[db], pH, vH[db]);
#pragma unroll
                for (int db = 0; db < 2; db++) mma16816(oacc[db], pH, vL[db]);
#pragma unroll
                for (int db = 0; db < 2; db++) mma16816(oacc[db], pL, vH[db]);
            }
            __syncthreads();
            if (nt < 3) { loadV(nt + 1); cpa_commit(); }
        }

        int row = qb * 16 + (lane >> 2);
#pragma unroll
        for (int db = 0; db < 2; db++) {
            int dv = dvh * 16 + db * 8 + (lane & 3) * 2;
            *(float2*)&g_act[(((size_t)bb * 512 + q0 + row) * 8 + hh) * 64 + dv] =
                make_float2(oacc[db][0], oacc[db][1]);
            *(float2*)&g_act[(((size_t)bb * 512 + q0 + row + 8) * 8 + hh) * 64 + dv] =
                make_float2(oacc[db][2], oacc[db][3]);
        }
    }
}

// ===========================================================================
// actcvt: g_act [b][i] fp32 -> g_aT [i][16 b] fp32, tf32-rounded (cvt.rna)
// ===========================================================================
__global__ void __launch_bounds__(256) actcvt()
{
    __shared__ float sm[16][65];
    const int tid = threadIdx.x;
    const int i0 = blockIdx.x * 64;

    for (int f = tid; f < 1024; f += 256) {
        int b = f >> 6, ii = f & 63;
        sm[b][ii] = g_act[(size_t)b * 262144 + i0 + ii];
    }
    __syncthreads();

    for (int f = tid; f < 512; f += 256) {
        int ii = f >> 3, bp = f & 7;
        uint2 t;
        t.x = cvt_tf32(sm[bp * 2][ii]);
        t.y = cvt_tf32(sm[bp * 2 + 1][ii]);
        *(uint2*)&g_aT[(size_t)(i0 + ii) * 16 + bp * 2] = t;
    }
}

// ===========================================================================
// fc_tf32: out[b][o] = sum_i act[b][i]*Wf[o][i] via mma.sync.m16n8k8 tf32.
// 256 thr (8 warps), grid (256 ksplit, 16 oblocks of 32). Sub-chunk = 128 k.
// Ring depth 3: slot = Wf fp32 [32 o][132 pad] (16896B) + act [128 k][24 pad]
// (12288B). Warp = (khalf = wid>>2, ogroup = wid&3): 8 mma per sc.
// A frags via scalar LDS (act pre-rounded); B via LDS + cvt.rna.
// Cross-khalf reduce via smem -> g_part (layout unchanged).
// ===========================================================================
#define FCT_WSLOT 16896
#define FCT_SLOT  29184                     // WSLOT + 128*96
#define FCT_RED   87552                     // 3 * FCT_SLOT
#define FCT_SMEM  91648                     // + 1024 floats red

__global__ void __launch_bounds__(256, 2) fc_kernel(const float* __restrict__ Wf)
{
    extern __shared__ char smc[];
    const uint32_t sb = smem_u32(smc);
    const int tid = threadIdx.x;
    const int wid = tid >> 5, lane = tid & 31;
    const int k0 = blockIdx.x * 1024;
    const int o0 = blockIdx.y * 32;
    const int khf = wid >> 2, og = wid & 3;

    auto loadSlot = [&](int sc) {
        const uint32_t base = sb + (uint32_t)(sc % 3) * FCT_SLOT;
        const float* wsrc = Wf + (size_t)o0 * 262144 + k0 + sc * 128;
#pragma unroll
        for (int i = 0; i < 4; i++) {
            int c = tid + i * 256;                 // 0..1023
            int row = c >> 5, sg = c & 31;
            cpa16(base + row * 528 + sg * 16,
                  wsrc + (size_t)row * 262144 + sg * 4);
        }
#pragma unroll
        for (int i = 0; i < 2; i++) {
            int c = tid + i * 256;                 // 0..511
            int row = c >> 2, sg = c & 3;
            cpa16(base + FCT_WSLOT + row * 96 + sg * 16,
                  g_aT + (size_t)(k0 + sc * 128 + row) * 16 + sg * 4);
        }
        cpa_commit();
    };
    loadSlot(0); loadSlot(1); loadSlot(2);

    float acc[4];
    acc[0] = acc[1] = acc[2] = acc[3] = 0.f;

    const int lk = lane & 3, lb = lane >> 2;

    for (int sc = 0; sc < 8; sc++) {
        if (sc <= 5) cpa_wait<2>();
        else if (sc == 6) cpa_wait<1>();
        else cpa_wait<0>();
        __syncthreads();

        const float* wsl = (const float*)(smc + (sc % 3) * FCT_SLOT);
        const uint32_t* asl = (const uint32_t*)(smc + (sc % 3) * FCT_SLOT + FCT_WSLOT);

#pragma unroll
        for (int ks = 0; ks < 8; ks++) {
            const int kk = khf * 64 + ks * 8;
            const int ka = kk + lk;
            uint32_t a0 = asl[ka * 24 + lb];
            uint32_t a1 = asl[ka * 24 + lb + 8];
            uint32_t a2 = asl[(ka + 4) * 24 + lb];
            uint32_t a3 = asl[(ka + 4) * 24 + lb + 8];
            float w0 = wsl[(og * 8 + lb) * 132 + kk + lk];
            float w1 = wsl[(og * 8 + lb) * 132 + kk + lk + 4];
            mma_tf32(acc, a0, a1, a2, a3, cvt_tf32(w0), cvt_tf32(w1));
        }
        __syncthreads();
        if (sc + 3 < 8) loadSlot(sc + 3);
    }

    // cross-khalf reduce: red [2 kh][16 b][32 o] floats
    float* red = (float*)(smc + FCT_RED);
    {
        int base = khf * 512 + (lane >> 2) * 32 + og * 8 + (lane & 3) * 2;
        red[base]             = acc[0];
        red[base + 1]         = acc[1];
        red[base + 8 * 32]    = acc[2];
        red[base + 8 * 32 + 1] = acc[3];
    }
    __syncthreads();
#pragma unroll
    for (int rep = 0; rep < 2; rep++) {
        int e = tid + rep * 256;                  // e = b*32 + o
        float s = red[e] + red[512 + e];
        int b = e >> 5, o = e & 31;
        g_part[((size_t)blockIdx.x * 512 + o0 + o) * 16 + b] = s;
    }
}

__global__ void __launch_bounds__(256) reduce_fc(const float* __restrict__ bf,
                                                 float* __restrict__ out)
{
    __shared__ float red[8][33];
    const int t = threadIdx.x;
    const int oi = blockIdx.x * 32 + (t & 31);
    const int part = t >> 5;
    const int o = oi >> 4, b = oi & 15;
    float s = 0.f;
#pragma unroll 8
    for (int ks = part * 32; ks < part * 32 + 32; ks++)
        s += g_part[((size_t)ks * 512 + o) * 16 + b];
    red[part][t & 31] = s;
    __syncthreads();
    if (t < 32) {
        float tot = 0.f;
#pragma unroll
        for (int j = 0; j < 8; j++) tot += red[j][t];
        int oo = blockIdx.x * 32 + t;
        out[(oo & 15) * 512 + (oo >> 4)] = tot + bf[oo >> 4];
    }
}

// ===========================================================================
extern "C" void kernel_launch(void* const* d_in, const int* in_sizes, int n_in,
                              void* d_out, int out_size)
{
    const float* q  = (const float*)d_in[0];
    const float* k  = (const float*)d_in[1];
    const float* v  = (const float*)d_in[2];
    const float* Wq = (const float*)d_in[3];
    const float* bq = (const float*)d_in[4];
    const float* Wk = (const float*)d_in[5];
    const float* bk = (const float*)d_in[6];
    const float* Wv = (const float*)d_in[7];
    const float* bv = (const float*)d_in[8];
    const float* Wf = (const float*)d_in[9];
    const float* bf = (const float*)d_in[10];
    float* out = (float*)d_out;

    cudaFuncSetAttribute(proj_mma, cudaFuncAttributeMaxDynamicSharedMemorySize, PJ_SMEM);
    cudaFuncSetAttribute(attn_kernel, cudaFuncAttributeMaxDynamicSharedMemorySize,
                         ATTN2_SMEM);
    cudaFuncSetAttribute(fc_kernel, cudaFuncAttributeMaxDynamicSharedMemorySize,
                         FCT_SMEM);

    cvt_kernel<<<13056, 256>>>(q, k, v, Wq, Wk, Wv);
    proj_mma<<<dim3(4, 64, 3), 256, PJ_SMEM>>>(bq, bk, bv);
    attn_kernel<<<dim3(8, 128), 512, ATTN2_SMEM>>>(out + 8192);
    actcvt<<<4096, 256>>>();
    fc_kernel<<<dim3(256, 16), 256, FCT_SMEM>>>(Wf);
    reduce_fc<<<256, 256>>>(bf, out);
}

// round 17
// speedup vs baseline: 1.2717x; 1.0039x over previous
#include <cuda_runtime.h>
#include <cuda_bf16.h>
#include <cstdint>

// ---------------------------------------------------------------------------
// MultiHeadAttention: B=16, L=512, D=512, H=8, DK=DV=64, TEMP=8
// out = ( output[16,512], attn[128,512,512] ) concatenated in d_out (fp32)
// R15: PV via tf32 mma (P straight from S-strip, V pre-rounded tf32 in proj)
// ---------------------------------------------------------------------------

typedef unsigned long long u64t;

// ------------------------- scratch (static device mem) ---------------------
__device__ __align__(16) float g_act[16 * 512 * 512];     // [b][i]
__device__ __align__(16) float g_part[256 * 512 * 16];    // [ksplit][o][b]
__device__ __align__(16) __nv_bfloat16 g_xhi[3 * 8192 * 512];
__device__ __align__(16) __nv_bfloat16 g_xlo[3 * 8192 * 512];
__device__ __align__(16) __nv_bfloat16 g_whi[3 * 512 * 512];
__device__ __align__(16) __nv_bfloat16 g_wlo[3 * 512 * 512];
// head-major bf16 hi/lo projections: [h*16+b][l][64]
__device__ __align__(16) __nv_bfloat16 g_qBh[128 * 512 * 64];
__device__ __align__(16) __nv_bfloat16 g_qBl[128 * 512 * 64];
__device__ __align__(16) __nv_bfloat16 g_kBh[128 * 512 * 64];
__device__ __align__(16) __nv_bfloat16 g_kBl[128 * 512 * 64];
// V head-major, tf32-rounded fp32: [h*16+b][l][64]
__device__ __align__(16) float g_vT[128 * 512 * 64];
// act transposed, tf32-rounded fp32: [i][16 b]
__device__ __align__(16) float g_aT[262144 * 16];

// ------------------------- helpers -----------------------------------------
__device__ __forceinline__ uint32_t smem_u32(const void* p) {
    uint32_t a;
    asm("{ .reg .u64 t; cvta.to.shared.u64 t, %1; cvt.u32.u64 %0, t; }"
        : "=r"(a) : "l"(p));
    return a;
}
__device__ __forceinline__ void ldm4(uint32_t* r, uint32_t addr) {
    asm volatile("ldmatrix.sync.aligned.m8n8.x4.shared.b16 {%0,%1,%2,%3}, [%4];"
                 : "=r"(r[0]), "=r"(r[1]), "=r"(r[2]), "=r"(r[3]) : "r"(addr));
}
__device__ __forceinline__ void mma16816(float* c, const uint32_t* a,
                                         const uint32_t* b) {
    asm volatile(
        "mma.sync.aligned.m16n8k16.row.col.f32.bf16.bf16.f32 "
        "{%0,%1,%2,%3}, {%4,%5,%6,%7}, {%8,%9}, {%0,%1,%2,%3};"
        : "+f"(c[0]), "+f"(c[1]), "+f"(c[2]), "+f"(c[3])
        : "r"(a[0]), "r"(a[1]), "r"(a[2]), "r"(a[3]), "r"(b[0]), "r"(b[1]));
}
__device__ __forceinline__ void mma_tf32(float* c, uint32_t a0, uint32_t a1,
                                         uint32_t a2, uint32_t a3,
                                         uint32_t b0, uint32_t b1) {
    asm volatile(
        "mma.sync.aligned.m16n8k8.row.col.f32.tf32.tf32.f32 "
        "{%0,%1,%2,%3}, {%4,%5,%6,%7}, {%8,%9}, {%0,%1,%2,%3};"
        : "+f"(c[0]), "+f"(c[1]), "+f"(c[2]), "+f"(c[3])
        : "r"(a0), "r"(a1), "r"(a2), "r"(a3), "r"(b0), "r"(b1));
}
__device__ __forceinline__ uint32_t cvt_tf32(float x) {
    uint32_t u;
    asm("cvt.rna.tf32.f32 %0, %1;" : "=r"(u) : "f"(x));
    return u;
}
__device__ __forceinline__ void cpa16(uint32_t sa, const void* ga) {
    asm volatile("cp.async.cg.shared.global [%0], [%1], 16;"
                 :: "r"(sa), "l"(ga) : "memory");
}
__device__ __forceinline__ void cpa_commit() {
    asm volatile("cp.async.commit_group;" ::: "memory");
}
template <int N>
__device__ __forceinline__ void cpa_wait() {
    asm volatile("cp.async.wait_group %0;" :: "n"(N) : "memory");
}

// ===========================================================================
// cvt_kernel: fp32 -> (bf16 hi, bf16 lo) split for X (q,k,v) and W (Wq,Wk,Wv)
// ===========================================================================
__global__ void __launch_bounds__(256) cvt_kernel(
    const float* __restrict__ q, const float* __restrict__ k,
    const float* __restrict__ v,
    const float* __restrict__ Wq, const float* __restrict__ Wk,
    const float* __restrict__ Wv)
{
    const int t = blockIdx.x * 256 + threadIdx.x;
    const int XN4 = 3 * 1048576;
    const int WN4 = 3 * 65536;
    if (t >= XN4 + WN4) return;

    const float* src;
    __nv_bfloat16 *dh, *dl;
    size_t off4;
    if (t < XN4) {
        int z = t >> 20, i = t & 1048575;
        src = (z == 0) ? q : (z == 1) ? k : v;
        dh = g_xhi + (size_t)z * 4194304; dl = g_xlo + (size_t)z * 4194304;
        off4 = i;
    } else {
        int t2 = t - XN4;
        int z = t2 >> 16, i = t2 & 65535;
        src = (z == 0) ? Wq : (z == 1) ? Wk : Wv;
        dh = g_whi + (size_t)z * 262144; dl = g_wlo + (size_t)z * 262144;
        off4 = i;
    }
    float4 x = *(const float4*)(src + off4 * 4);
    float a[4] = { x.x, x.y, x.z, x.w };
    __nv_bfloat16 h[4], l[4];
#pragma unroll
    for (int j = 0; j < 4; j++) {
        h[j] = __float2bfloat16(a[j]);
        l[j] = __float2bfloat16(a[j] - __bfloat162float(h[j]));
    }
    __nv_bfloat162* ph = (__nv_bfloat162*)(dh + off4 * 4);
    __nv_bfloat162* pl = (__nv_bfloat162*)(dl + off4 * 4);
    ph[0] = __halves2bfloat162(h[0], h[1]); ph[1] = __halves2bfloat162(h[2], h[3]);
    pl[0] = __halves2bfloat162(l[0], l[1]); pl[1] = __halves2bfloat162(l[2], l[3]);
}

// ===========================================================================
// proj_mma v2 (R12): K-chunk 32, 2 CTAs/SM.
// z==2 (V) epilogue emits tf32-rounded fp32 to g_vT; else bf16 hi/lo.
// ===========================================================================
#define RS2    80
#define MHALF2 10240
#define CH_BUF2 40960
#define PJ_SMEM (2 * CH_BUF2)

__global__ void __launch_bounds__(256, 2) proj_mma(
    const float* __restrict__ bq, const float* __restrict__ bk,
    const float* __restrict__ bv)
{
    extern __shared__ char smem[];
    const uint32_t sb = smem_u32(smem);
    const int tid = threadIdx.x;
    const int wid = tid >> 5, lane = tid & 31;
    const int warp_m = wid & 3, warp_n = wid >> 2;

    const int z = blockIdx.z;
    const int m0 = blockIdx.y * 128;
    const int n0 = blockIdx.x * 128;
    const float* bias = (z == 0) ? bq : (z == 1) ? bk : bv;
    __nv_bfloat16* dH = (z == 0) ? g_qBh : g_kBh;
    __nv_bfloat16* dL = (z == 0) ? g_qBl : g_kBl;

    const __nv_bfloat16* gm[4] = {
        g_xhi + ((size_t)z * 8192 + m0) * 512,
        g_xlo + ((size_t)z * 8192 + m0) * 512,
        g_whi + ((size_t)z * 512 + n0) * 512,
        g_wlo + ((size_t)z * 512 + n0) * 512 };

    const uint32_t a_row  = lane & 15;
    const uint32_t a_koff = (lane >> 4) * 16;
    const uint32_t b_nrow = ((lane >> 4) * 8) + (lane & 7);
    const uint32_t b_koff = ((lane >> 3) & 1) * 16;

    float acc[2][8][4];
#pragma unroll
    for (int mt = 0; mt < 2; mt++)
#pragma unroll
        for (int nt = 0; nt < 8; nt++)
#pragma unroll
            for (int j = 0; j < 4; j++) acc[mt][nt][j] = 0.f;

    auto load_chunk = [&](int c) {
        const int kc = c * 32;
        const uint32_t base = sb + (uint32_t)(c & 1) * CH_BUF2;
#pragma unroll
        for (int i = 0; i < 8; i++) {
            int idx = tid + i * 256;
            int mat = idx >> 9, r2 = idx & 511;
            int row = r2 >> 2, seg = r2 & 3;
            cpa16(base + mat * MHALF2 + row * RS2 + seg * 16,
                  gm[mat] + (size_t)row * 512 + kc + seg * 8);
        }
        cpa_commit();
    };

    load_chunk(0);
    load_chunk(1);

    for (int c = 0; c < 16; c++) {
        if (c < 15) cpa_wait<1>(); else cpa_wait<0>();
        __syncthreads();

        const uint32_t bufb = sb + (uint32_t)(c & 1) * CH_BUF2;
        const uint32_t aBase = bufb + (warp_m * 32 + a_row) * RS2 + a_koff;
        const uint32_t bBase = bufb + 2 * MHALF2 +
                               (warp_n * 64 + b_nrow) * RS2 + b_koff;
#pragma unroll
        for (int ks = 0; ks < 2; ks++) {
            uint32_t aH[2][4], aL[2][4], bH[8][2], bL[8][2];
#pragma unroll
            for (int mt = 0; mt < 2; mt++) {
                uint32_t ad = aBase + mt * 16 * RS2 + ks * 32;
                ldm4(aH[mt], ad);
                ldm4(aL[mt], ad + MHALF2);
            }
#pragma unroll
            for (int nb = 0; nb < 4; nb++) {
                uint32_t bd = bBase + nb * 16 * RS2 + ks * 32;
                uint32_t r[4];
                ldm4(r, bd);
                bH[2 * nb][0] = r[0]; bH[2 * nb][1] = r[1];
                bH[2 * nb + 1][0] = r[2]; bH[2 * nb + 1][1] = r[3];
                ldm4(r, bd + MHALF2);
                bL[2 * nb][0] = r[0]; bL[2 * nb][1] = r[1];
                bL[2 * nb + 1][0] = r[2]; bL[2 * nb + 1][1] = r[3];
            }
#pragma unroll
            for (int mt = 0; mt < 2; mt++)
#pragma unroll
                for (int nt = 0; nt < 8; nt++) {
                    mma16816(acc[mt][nt], aH[mt], bH[nt]);
                    mma16816(acc[mt][nt], aH[mt], bL[nt]);
                    mma16816(acc[mt][nt], aL[mt], bH[nt]);
                }
        }
        __syncthreads();
        if (c + 2 < 16) load_chunk(c + 2);
    }

    float* stage = (float*)smem;
#pragma unroll
    for (int mt = 0; mt < 2; mt++)
#pragma unroll
        for (int nt = 0; nt < 8; nt++) {
            int row = warp_m * 32 + mt * 16 + (lane >> 2);
            int col = warp_n * 64 + nt * 8 + (lane & 3) * 2;
            *(float2*)&stage[row * 132 + col] =
                make_float2(acc[mt][nt][0], acc[mt][nt][1]);
            *(float2*)&stage[(row + 8) * 132 + col] =
                make_float2(acc[mt][nt][2], acc[mt][nt][3]);
        }
    __syncthreads();

    for (int f = tid; f < 4096; f += 256) {
        int row = f >> 5, c4 = f & 31;
        int nn = c4 * 4;
        int rg = m0 + row, bbi = rg >> 9, ll = rg & 511;
        int hh2 = (n0 + nn) >> 6, d = nn & 63;
        float r[4];
#pragma unroll
        for (int j = 0; j < 4; j++)
            r[j] = stage[row * 132 + nn + j] + __ldg(&bias[n0 + nn + j]);
        size_t off = (((size_t)hh2 * 16 + bbi) * 512 + ll) * 64 + d;
        if (z == 2) {
            float4 t;
            t.x = __uint_as_float(cvt_tf32(r[0]));
            t.y = __uint_as_float(cvt_tf32(r[1]));
            t.z = __uint_as_float(cvt_tf32(r[2]));
            t.w = __uint_as_float(cvt_tf32(r[3]));
            *(float4*)&g_vT[off] = t;
        } else {
            __nv_bfloat16 h[4], l[4];
#pragma unroll
            for (int j = 0; j < 4; j++) {
                h[j] = __float2bfloat16(r[j]);
                l[j] = __float2bfloat16(r[j] - __bfloat162float(h[j]));
            }
            __nv_bfloat162 hp0 = __halves2bfloat162(h[0], h[1]);
            __nv_bfloat162 hp1 = __halves2bfloat162(h[2], h[3]);
            __nv_bfloat162 lp0 = __halves2bfloat162(l[0], l[1]);
            __nv_bfloat162 lp1 = __halves2bfloat162(l[2], l[3]);
            uint2 uh, ul;
            uh.x = *(uint32_t*)&hp0; uh.y = *(uint32_t*)&hp1;
            ul.x = *(uint32_t*)&lp0; ul.y = *(uint32_t*)&lp1;
            *(uint2*)&dH[off] = uh;
            *(uint2*)&dL[off] = ul;
        }
    }
}

// ===========================================================================
// attn v4: CTA per (hb, qtile 64), 512 threads.
// Phase 1 QK^T bf16-split (unchanged). Phase 3 PV via tf32 mma: P read
// directly from S strip (cvt.rna on the fly), V fp32 tiles [n][72] pad.
// ===========================================================================
#define AQ   133120
#define AC   151552
#define AIVF 56320
#define ATTN2_SMEM 225536

__global__ void __launch_bounds__(512) attn_kernel(float* __restrict__ attn_out)
{
    extern __shared__ char smb[];
    float* smf = (float*)smb;
    const uint32_t sb = smem_u32(smb);
    const int tid = threadIdx.x;
    const int wid = tid >> 5, lane = tid & 31;
    const int hb = blockIdx.y;
    const int q0 = blockIdx.x * 64;
    const int bb = hb & 15, hh = hb >> 4;

    const __nv_bfloat16* kh = g_kBh + (size_t)hb * 512 * 64;
    const __nv_bfloat16* kl = g_kBl + (size_t)hb * 512 * 64;
    const float* vt = g_vT + (size_t)hb * 512 * 64;

    auto loadK = [&](int nt) {
        const uint32_t base = sb + AC + (uint32_t)(nt & 1) * 36864;
#pragma unroll
        for (int i = 0; i < 4; i++) {
            int f = tid + i * 512;
            int mat = f >> 10, idx = f & 1023;
            int rw = idx >> 3, sg = idx & 7;
            const __nv_bfloat16* g = mat ? kl : kh;
            cpa16(base + mat * 18432 + rw * 144 + sg * 16,
                  g + (size_t)(nt * 128 + rw) * 64 + sg * 8);
        }
    };
    // V tile fp32 [128 n][72 pad floats] = 36864 B, double buffered in AC
    auto loadV = [&](int nt) {
        const uint32_t base = sb + AC + (uint32_t)(nt & 1) * 36864;
#pragma unroll
        for (int i = 0; i < 4; i++) {
            int f = tid + i * 512;
            int rw = f >> 4, sg = f & 15;
            cpa16(base + rw * 288 + sg * 16,
                  vt + (size_t)(nt * 128 + rw) * 64 + sg * 4);
        }
    };

    {
        const __nv_bfloat16* qhp = g_qBh + ((size_t)hb * 512 + q0) * 64;
        const __nv_bfloat16* qlp = g_qBl + ((size_t)hb * 512 + q0) * 64;
#pragma unroll
        for (int i = 0; i < 2; i++) {
            int f = tid + i * 512;
            int mat = f >> 9, idx = f & 511;
            int rw = idx >> 3, sg = idx & 7;
            const __nv_bfloat16* g = mat ? qlp : qhp;
            cpa16(sb + AQ + mat * 9216 + rw * 144 + sg * 16,
                  g + (size_t)rw * 64 + sg * 8);
        }
        loadK(0); cpa_commit();
        loadK(1); cpa_commit();
    }

    // ---- Phase 1: S = QK^T / 8 via bf16-split mma ----
    {
        const int qb = wid & 3, nq = wid >> 2;
        const uint32_t aAddr = sb + AQ +
            (uint32_t)((qb * 16 + (lane & 15)) * 144 + ((lane >> 4) * 8) * 2);
        cpa_wait<1>(); __syncthreads();
        uint32_t aH[4][4], aL[4][4];
#pragma unroll
        for (int ks = 0; ks < 4; ks++) {
            ldm4(aH[ks], aAddr + ks * 32);
            ldm4(aL[ks], aAddr + 9216 + ks * 32);
        }
        const uint32_t bOff = (uint32_t)(
            (nq * 32 + ((lane >> 4) * 8) + (lane & 7)) * 144 +
            (((lane >> 3) & 1) * 8) * 2);

        for (int nt = 0; nt < 4; nt++) {
            if (nt == 3) { cpa_wait<0>(); __syncthreads(); }
            else if (nt > 0) { cpa_wait<1>(); __syncthreads(); }
            const uint32_t Bb = sb + AC + (uint32_t)(nt & 1) * 36864 + bOff;
            float acc[4][4];
#pragma unroll
            for (int nb = 0; nb < 4; nb++)
#pragma unroll
                for (int j = 0; j < 4; j++) acc[nb][j] = 0.f;
#pragma unroll
            for (int ks = 0; ks < 4; ks++) {
                uint32_t bH[4][2], bL[4][2];
#pragma unroll
                for (int nb4 = 0; nb4 < 2; nb4++) {
                    uint32_t r[4];
                    ldm4(r, Bb + nb4 * 16 * 144 + ks * 32);
                    bH[2 * nb4][0] = r[0]; bH[2 * nb4][1] = r[1];
                    bH[2 * nb4 + 1][0] = r[2]; bH[2 * nb4 + 1][1] = r[3];
                    ldm4(r, Bb + 18432 + nb4 * 16 * 144 + ks * 32);
                    bL[2 * nb4][0] = r[0]; bL[2 * nb4][1] = r[1];
                    bL[2 * nb4 + 1][0] = r[2]; bL[2 * nb4 + 1][1] = r[3];
                }
#pragma unroll
                for (int nb = 0; nb < 4; nb++) mma16816(acc[nb], aH[ks], bH[nb]);
#pragma unroll
                for (int nb = 0; nb < 4; nb++) mma16816(acc[nb], aH[ks], bL[nb]);
#pragma unroll
                for (int nb = 0; nb < 4; nb++) mma16816(acc[nb], aL[ks], bH[nb]);
            }
            int row = qb * 16 + (lane >> 2);
#pragma unroll
            for (int nb = 0; nb < 4; nb++) {
                int col = nt * 128 + nq * 32 + nb * 8 + (lane & 3) * 2;
                *(float2*)&smf[row * 520 + col] =
                    make_float2(acc[nb][0] * 0.125f, acc[nb][1] * 0.125f);
                *(float2*)&smf[(row + 8) * 520 + col] =
                    make_float2(acc[nb][2] * 0.125f, acc[nb][3] * 0.125f);
            }
            __syncthreads();
            if (nt < 2) { loadK(nt + 2); cpa_commit(); }
        }
    }

    loadV(0); cpa_commit();

    // ---- Phase 2: softmax + attn writeback (16 warps x 4 rows) ----
    {
        for (int qi = 0; qi < 4; qi++) {
            int ql = wid * 4 + qi;
            float* srow = &smf[ql * 520];
            float m = -3.4e38f;
#pragma unroll
            for (int s = 0; s < 4; s++) {
                float4 v = *(const float4*)&srow[(s * 32 + lane) * 4];
                m = fmaxf(m, fmaxf(fmaxf(v.x, v.y), fmaxf(v.z, v.w)));
            }
#pragma unroll
            for (int off = 16; off >= 1; off >>= 1)
                m = fmaxf(m, __shfl_xor_sync(0xffffffffu, m, off));
            float sum = 0.f;
#pragma unroll
            for (int s = 0; s < 4; s++) {
                float4* p = (float4*)&srow[(s * 32 + lane) * 4];
                float4 v = *p;
                v.x = __expf(v.x - m); v.y = __expf(v.y - m);
                v.z = __expf(v.z - m); v.w = __expf(v.w - m);
                *p = v;
                sum += v.x + v.y + v.z + v.w;
            }
#pragma unroll
            for (int off = 16; off >= 1; off >>= 1)
                sum += __shfl_xor_sync(0xffffffffu, sum, off);
            float iv = 1.0f / sum;
            if (lane == 0) smf[AIVF + ql] = iv;
            float* drow = attn_out + ((size_t)hb * 512 + q0 + ql) * 512;
#pragma unroll
            for (int s = 0; s < 4; s++) {
                float4 v = *(const float4*)&srow[(s * 32 + lane) * 4];
                v.x *= iv; v.y *= iv; v.z *= iv; v.w *= iv;
                *(float4*)&drow[(s * 32 + lane) * 4] = v;
            }
        }
    }
    __syncthreads();

    // ---- Phase 3: O = (S_exp V) * iv via tf32 mma ----
    {
        const int qb = wid & 3, dvh = wid >> 2;
        const int lk = lane & 3, lb = lane >> 2;
        const int r0 = qb * 16 + lb;
        const int dv0 = dvh * 16;
        const float iv0 = smf[AIVF + r0];
        const float iv1 = smf[AIVF + r0 + 8];

        float oacc[2][4];
#pragma unroll
        for (int db = 0; db < 2; db++)
#pragma unroll
            for (int j = 0; j < 4; j++) oacc[db][j] = 0.f;

        for (int nt = 0; nt < 4; nt++) {
            cpa_wait<0>(); __syncthreads();
            if (nt < 3) { loadV(nt + 1); cpa_commit(); }
            const float* Vs = (const float*)(smb + AC + (nt & 1) * 36864);
#pragma unroll
            for (int ks = 0; ks < 16; ks++) {
                int col = nt * 128 + ks * 8 + lk;
                uint32_t a0 = cvt_tf32(smf[r0 * 520 + col]);
                uint32_t a1 = cvt_tf32(smf[(r0 + 8) * 520 + col]);
                uint32_t a2 = cvt_tf32(smf[r0 * 520 + col + 4]);
                uint32_t a3 = cvt_tf32(smf[(r0 + 8) * 520 + col + 4]);
#pragma unroll
                for (int db = 0; db < 2; db++) {
                    uint32_t b0 = __float_as_uint(
                        Vs[(ks * 8 + lk) * 72 + dv0 + db * 8 + lb]);
                    uint32_t b1 = __float_as_uint(
                        Vs[(ks * 8 + 4 + lk) * 72 + dv0 + db * 8 + lb]);
                    mma_tf32(oacc[db], a0, a1, a2, a3, b0, b1);
                }
            }
            __syncthreads();
        }

#pragma unroll
        for (int db = 0; db < 2; db++) {
            int dv = dv0 + db * 8 + lk * 2;
            *(float2*)&g_act[(((size_t)bb * 512 + q0 + r0) * 8 + hh) * 64 + dv] =
                make_float2(oacc[db][0] * iv0, oacc[db][1] * iv0);
            *(float2*)&g_act[(((size_t)bb * 512 + q0 + r0 + 8) * 8 + hh) * 64 + dv] =
                make_float2(oacc[db][2] * iv1, oacc[db][3] * iv1);
        }
    }
}

// ===========================================================================
// actcvt: g_act [b][i] fp32 -> g_aT [i][16 b] fp32, tf32-rounded (cvt.rna)
// ===========================================================================
__global__ void __launch_bounds__(256) actcvt()
{
    __shared__ float sm[16][65];
    const int tid = threadIdx.x;
    const int i0 = blockIdx.x * 64;

    for (int f = tid; f < 1024; f += 256) {
        int b = f >> 6, ii = f & 63;
        sm[b][ii] = g_act[(size_t)b * 262144 + i0 + ii];
    }
    __syncthreads();

    for (int f = tid; f < 512; f += 256) {
        int ii = f >> 3, bp = f & 7;
        uint2 t;
        t.x = cvt_tf32(sm[bp * 2][ii]);
        t.y = cvt_tf32(sm[bp * 2 + 1][ii]);
        *(uint2*)&g_aT[(size_t)(i0 + ii) * 16 + bp * 2] = t;
    }
}

// ===========================================================================
// fc_tf32 (R14): out[b][o] = sum_i act[b][i]*Wf[o][i] via mma tf32.
// ===========================================================================
#define FCT_WSLOT 16896
#define FCT_SLOT  29184
#define FCT_RED   87552
#define FCT_SMEM  91648

__global__ void __launch_bounds__(256, 2) fc_kernel(const float* __restrict__ Wf)
{
    extern __shared__ char smc[];
    const uint32_t sb = smem_u32(smc);
    const int tid = threadIdx.x;
    const int wid = tid >> 5, lane = tid & 31;
    const int k0 = blockIdx.x * 1024;
    const int o0 = blockIdx.y * 32;
    const int khf = wid >> 2, og = wid & 3;

    auto loadSlot = [&](int sc) {
        const uint32_t base = sb + (uint32_t)(sc % 3) * FCT_SLOT;
        const float* wsrc = Wf + (size_t)o0 * 262144 + k0 + sc * 128;
#pragma unroll
        for (int i = 0; i < 4; i++) {
            int c = tid + i * 256;
            int row = c >> 5, sg = c & 31;
            cpa16(base + row * 528 + sg * 16,
                  wsrc + (size_t)row * 262144 + sg * 4);
        }
#pragma unroll
        for (int i = 0; i < 2; i++) {
            int c = tid + i * 256;
            int row = c >> 2, sg = c & 3;
            cpa16(base + FCT_WSLOT + row * 96 + sg * 16,
                  g_aT + (size_t)(k0 + sc * 128 + row) * 16 + sg * 4);
        }
        cpa_commit();
    };
    loadSlot(0); loadSlot(1); loadSlot(2);

    float acc[4];
    acc[0] = acc[1] = acc[2] = acc[3] = 0.f;

    const int lk = lane & 3, lb = lane >> 2;

    for (int sc = 0; sc < 8; sc++) {
        if (sc <= 5) cpa_wait<2>();
        else if (sc == 6) cpa_wait<1>();
        else cpa_wait<0>();
        __syncthreads();

        const float* wsl = (const float*)(smc + (sc % 3) * FCT_SLOT);
        const uint32_t* asl = (const uint32_t*)(smc + (sc % 3) * FCT_SLOT + FCT_WSLOT);

#pragma unroll
        for (int ks = 0; ks < 8; ks++) {
            const int kk = khf * 64 + ks * 8;
            const int ka = kk + lk;
            uint32_t a0 = asl[ka * 24 + lb];
            uint32_t a1 = asl[ka * 24 + lb + 8];
            uint32_t a2 = asl[(ka + 4) * 24 + lb];
            uint32_t a3 = asl[(ka + 4) * 24 + lb + 8];
            float w0 = wsl[(og * 8 + lb) * 132 + kk + lk];
            float w1 = wsl[(og * 8 + lb) * 132 + kk + lk + 4];
            mma_tf32(acc, a0, a1, a2, a3, cvt_tf32(w0), cvt_tf32(w1));
        }
        __syncthreads();
        if (sc + 3 < 8) loadSlot(sc + 3);
    }

    float* red = (float*)(smc + FCT_RED);
    {
        int base = khf * 512 + (lane >> 2) * 32 + og * 8 + (lane & 3) * 2;
        red[base]              = acc[0];
        red[base + 1]          = acc[1];
        red[base + 8 * 32]     = acc[2];
        red[base + 8 * 32 + 1] = acc[3];
    }
    __syncthreads();
#pragma unroll
    for (int rep = 0; rep < 2; rep++) {
        int e = tid + rep * 256;
        float s = red[e] + red[512 + e];
        int b = e >> 5, o = e & 31;
        g_part[((size_t)blockIdx.x * 512 + o0 + o) * 16 + b] = s;
    }
}

__global__ void __launch_bounds__(256) reduce_fc(const float* __restrict__ bf,
                                                 float* __restrict__ out)
{
    __shared__ float red[8][33];
    const int t = threadIdx.x;
    const int oi = blockIdx.x * 32 + (t & 31);
    const int part = t >> 5;
    const int o = oi >> 4, b = oi & 15;
    float s = 0.f;
#pragma unroll 8
    for (int ks = part * 32; ks < part * 32 + 32; ks++)
        s += g_part[((size_t)ks * 512 + o) * 16 + b];
    red[part][t & 31] = s;
    __syncthreads();
    if (t < 32) {
        float tot = 0.f;
#pragma unroll
        for (int j = 0; j < 8; j++) tot += red[j][t];
        int oo = blockIdx.x * 32 + t;
        out[(oo & 15) * 512 + (oo >> 4)] = tot + bf[oo >> 4];
    }
}

// ===========================================================================
extern "C" void kernel_launch(void* const* d_in, const int* in_sizes, int n_in,
                              void* d_out, int out_size)
{
    const float* q  = (const float*)d_in[0];
    const float* k  = (const float*)d_in[1];
    const float* v  = (const float*)d_in[2];
    const float* Wq = (const float*)d_in[3];
    const float* bq = (const float*)d_in[4];
    const float* Wk = (const float*)d_in[5];
    const float* bk = (const float*)d_in[6];
    const float* Wv = (const float*)d_in[7];
    const float* bv = (const float*)d_in[8];
    const float* Wf = (const float*)d_in[9];
    const float* bf = (const float*)d_in[10];
    float* out = (float*)d_out;

    cudaFuncSetAttribute(proj_mma, cudaFuncAttributeMaxDynamicSharedMemorySize, PJ_SMEM);
    cudaFuncSetAttribute(attn_kernel, cudaFuncAttributeMaxDynamicSharedMemorySize,
                         ATTN2_SMEM);
    cudaFuncSetAttribute(fc_kernel, cudaFuncAttributeMaxDynamicSharedMemorySize,
                         FCT_SMEM);

    cvt_kernel<<<13056, 256>>>(q, k, v, Wq, Wk, Wv);
    proj_mma<<<dim3(4, 64, 3), 256, PJ_SMEM>>>(bq, bk, bv);
    attn_kernel<<<dim3(8, 128), 512, ATTN2_SMEM>>>(out + 8192);
    actcvt<<<4096, 256>>>();
    fc_kernel<<<dim3(256, 16), 256, FCT_SMEM>>>(Wf);
    reduce_fc<<<256, 256>>>(bf, out);
}